// round 11
// baseline (speedup 1.0000x reference)
#include <cuda_runtime.h>
#include <cuda_fp16.h>
#include <cstdint>

#define N_NODES 20000
#define READ_LEN 64
#define N_EDGES 320000
#define DIM 128
#define KSZ 20
#define CONV_T (READ_LEN - KSZ + 1)
#define N_LAYERS 4
#define EPS_BN 1e-5f
#define EPS_AGG 1e-6f

#define SBF 136   // half smem row stride (272B): 16B-aligned rows, ldsm conflict-free
#define SCF 132   // fp32 C smem row stride

// ---------------- device scratch ----------------
__device__ float g_h[N_NODES * DIM];
__device__ float g_e[(size_t)N_EDGES * DIM];
__device__ half  g_ehat[(size_t)N_EDGES * DIM];      // fp16 ehat
__device__ float g_Ah[N_NODES * DIM];
__device__ float g_Bh[N_NODES * DIM];
__device__ float g_Dh[N_NODES * DIM];
__device__ float g_Eh[N_NODES * DIM];
__device__ float g_t[N_NODES * DIM];
__device__ float g_wsum[4 * KSZ * DIM];
__device__ float g_W2[10 * 16 * DIM];
__device__ half  g_Whi[20 * 128 * SBF];              // pre-split weights (smem image)
__device__ float g_stats[2 * DIM];                   // zero-init; bn_final restores zeros
__device__ float g_bn_scale[DIM];
__device__ float g_bn_shift[DIM];
__device__ int g_cnt[N_NODES];
__device__ int g_off[N_NODES + 1];
__device__ int g_cur[N_NODES];
__device__ int g_eids[N_EDGES];

// ---------------- mma helpers ----------------
__device__ __forceinline__ unsigned s2u(const void* p)
{
    return (unsigned)__cvta_generic_to_shared(p);
}
__device__ __forceinline__ void ldsm4(unsigned* r, unsigned addr)
{
    asm volatile("ldmatrix.sync.aligned.m8n8.x4.shared.b16 {%0,%1,%2,%3}, [%4];"
                 : "=r"(r[0]), "=r"(r[1]), "=r"(r[2]), "=r"(r[3]) : "r"(addr));
}
__device__ __forceinline__ void mma16816(float* c, const unsigned* a, const unsigned* b)
{
    asm volatile("mma.sync.aligned.m16n8k16.row.col.f32.f16.f16.f32 "
                 "{%0,%1,%2,%3}, {%4,%5,%6,%7}, {%8,%9}, {%0,%1,%2,%3};"
                 : "+f"(c[0]), "+f"(c[1]), "+f"(c[2]), "+f"(c[3])
                 : "r"(a[0]), "r"(a[1]), "r"(a[2]), "r"(a[3]), "r"(b[0]), "r"(b[1]));
}

// pack 4 fp32 into hi/lo fp16 pairs and store to smem tile offset
__device__ __forceinline__ void split_store(half* hi, half* lo, int off4, float4 v)
{
    half hx = __float2half_rn(v.x), hy = __float2half_rn(v.y);
    half hz = __float2half_rn(v.z), hw = __float2half_rn(v.w);
    half2 hp0 = __halves2half2(hx, hy), hp1 = __halves2half2(hz, hw);
    half2 lp0 = __floats2half2_rn(v.x - __half2float(hx), v.y - __half2float(hy));
    half2 lp1 = __floats2half2_rn(v.z - __half2float(hz), v.w - __half2float(hw));
    *(uint2*)(hi + off4) = make_uint2(*(unsigned*)&hp0, *(unsigned*)&hp1);
    *(uint2*)(lo + off4) = make_uint2(*(unsigned*)&lp0, *(unsigned*)&lp1);
}

// split fp32 tile [rows<=128][128] into hi/lo fp16 smem tiles (512 threads)
__device__ __forceinline__ void split_tileA(const float* __restrict__ g, int rows,
                                            half* hi, half* lo, int tid)
{
#pragma unroll
    for (int i = tid; i < 128 * 32; i += 512) {
        int r = i >> 5, c = (i & 31) << 2;
        float4 v = make_float4(0.f, 0.f, 0.f, 0.f);
        if (r < rows) v = *(const float4*)(g + r * 128 + c);
        split_store(hi, lo, r * SBF + c, v);
    }
}

// mainloop (per warp, 32x32 tile): acc += Ahi*Whi + Alo*Whi; A frags reused (regs<=64)
__device__ __forceinline__ void mma_mainloop(const half* ahi, const half* alo,
                                             const half* whi,
                                             int m0w, int n0w, int lane,
                                             float acc[2][4][4])
{
    int aoff = (lane & 15) * SBF + (lane >> 4) * 8;
    int boff = ((lane & 7) + ((lane >> 4) << 3)) * SBF + ((lane >> 3) & 1) * 8;
#pragma unroll
    for (int kt = 0; kt < 8; kt++) {
        unsigned bf[2][4];
#pragma unroll
        for (int np = 0; np < 2; np++) {
            int o = (n0w + np * 16) * SBF + boff + kt * 16;
            ldsm4(bf[np], s2u(whi + o));
        }
        unsigned af[2][4];
#pragma unroll
        for (int ms = 0; ms < 2; ms++) {
            int o = (m0w + ms * 16) * SBF + aoff + kt * 16;
            ldsm4(af[ms], s2u(ahi + o));
        }
#pragma unroll
        for (int ms = 0; ms < 2; ms++)
#pragma unroll
            for (int nt = 0; nt < 4; nt++)
                mma16816(acc[ms][nt], af[ms], &bf[nt >> 1][(nt & 1) * 2]);
#pragma unroll
        for (int ms = 0; ms < 2; ms++) {
            int o = (m0w + ms * 16) * SBF + aoff + kt * 16;
            ldsm4(af[ms], s2u(alo + o));      // overwrite hi frags
        }
#pragma unroll
        for (int ms = 0; ms < 2; ms++)
#pragma unroll
            for (int nt = 0; nt < 4; nt++)
                mma16816(acc[ms][nt], af[ms], &bf[nt >> 1][(nt & 1) * 2]);
    }
}

// ---------------- prep ----------------
__global__ void k_wsum(const float* __restrict__ emb, const float* __restrict__ cw)
{
    int idx = blockIdx.x * 256 + threadIdx.x;
    if (idx >= 4 * KSZ * DIM) return;
    int d = idx & 127;
    int bk = idx >> 7;
    int k = bk % KSZ, b = bk / KSZ;
    float s = 0.f;
#pragma unroll
    for (int c = 0; c < 3; c++) s += emb[b * 3 + c] * cw[d * 3 * KSZ + c * KSZ + k];
    g_wsum[idx] = s;
}

__global__ void k_wsplit(const float* __restrict__ Aw, const float* __restrict__ Bw,
                         const float* __restrict__ Cw, const float* __restrict__ Dw,
                         const float* __restrict__ Ew)
{
    int m = blockIdx.x, tid = threadIdx.x;   // 20 blocks
    int lay = m / 5, which = m % 5;
    const float* srcs[5] = {Aw, Bw, Dw, Ew, Cw};
    const float* src = srcs[which] + lay * DIM * DIM;
    half* dst = g_Whi + (size_t)m * 128 * SBF;
    for (int i = tid; i < 128 * 128; i += 256) {
        int r = i >> 7, c = i & 127;
        dst[r * SBF + c] = __float2half_rn(src[i]);
    }
}

__global__ void k_W2()
{
    int idx = blockIdx.x * 256 + threadIdx.x;
    if (idx >= 10 * 16 * DIM) return;
    int d = idx & 127;
    int r = idx >> 7;
    int c2 = r & 15, k2 = r >> 4;
    int a = c2 >> 2, b = c2 & 3;
    g_W2[idx] = g_wsum[(a * KSZ + 2 * k2) * DIM + d] + g_wsum[(b * KSZ + 2 * k2 + 1) * DIM + d];
}

__global__ __launch_bounds__(512) void k_seq(const int* __restrict__ reads,
                                             const float* __restrict__ conv_b)
{
    extern __shared__ float sm[];
    float* sW2 = sm;
    int* scode = (int*)(sm + 10 * 16 * DIM);
    int* spc = scode + 512;
    int tid = threadIdx.x;

    for (int i = tid; i < (10 * 16 * DIM) / 4; i += 512)
        ((float4*)sW2)[i] = ((const float4*)g_W2)[i];

    int nl = tid >> 6, l = tid & 63;
    int n = blockIdx.x * 8 + nl;
    scode[tid] = reads[n * READ_LEN + l];
    __syncthreads();
    if (l < 63) spc[tid] = (scode[tid] * 4 + scode[tid + 1]) << 7;
    __syncthreads();

    int dp = tid & 63;
    const float* wd = sW2 + dp * 2;
    const int* pc = spc + nl * 64;
    float m0 = -3.4e38f, m1 = -3.4e38f;
#pragma unroll
    for (int t = 0; t < CONV_T; t++) {
        float s0 = 0.f, s1 = 0.f;
#pragma unroll
        for (int k2 = 0; k2 < 10; k2++) {
            float2 v = *(const float2*)(wd + pc[t + 2 * k2] + k2 * 2048);
            s0 += v.x; s1 += v.y;
        }
        m0 = fmaxf(m0, s0);
        m1 = fmaxf(m1, s1);
    }
    float2 bv = *(const float2*)(conv_b + dp * 2);
    float2 hv;
    hv.x = fmaxf(m0 + bv.x, 0.f);
    hv.y = fmaxf(m1 + bv.y, 0.f);
    *(float2*)(g_h + n * DIM + dp * 2) = hv;
}

// ---------------- CSR build by dst ----------------
__global__ void k_csr_zero()
{
    int i = blockIdx.x * 256 + threadIdx.x;
    if (i < N_NODES) g_cnt[i] = 0;
}
__global__ void k_hist(const int* __restrict__ dst)
{
    int i = blockIdx.x * 256 + threadIdx.x;
    if (i < N_EDGES) atomicAdd(&g_cnt[dst[i]], 1);
}
__global__ __launch_bounds__(1024) void k_scan()
{
    __shared__ int sd[1024];
    int tid = threadIdx.x;
    int carry = 0;
    for (int base = 0; base < N_NODES; base += 1024) {
        int i = base + tid;
        int v = (i < N_NODES) ? g_cnt[i] : 0;
        __syncthreads();
        sd[tid] = v;
        __syncthreads();
        for (int ofs = 1; ofs < 1024; ofs <<= 1) {
            int t = (tid >= ofs) ? sd[tid - ofs] : 0;
            __syncthreads();
            sd[tid] += t;
            __syncthreads();
        }
        if (i < N_NODES) {
            int ex = carry + sd[tid] - v;
            g_off[i] = ex;
            g_cur[i] = ex;
        }
        carry += sd[1023];
    }
    if (tid == 0) g_off[N_NODES] = carry;
}
__global__ void k_scatter(const int* __restrict__ dst)
{
    int i = blockIdx.x * 256 + threadIdx.x;
    if (i < N_EDGES) {
        int p = atomicAdd(&g_cur[dst[i]], 1);
        g_eids[p] = i;
    }
}

// ---------------- BN finalize (restores g_stats zero invariant) ----------------
__global__ __launch_bounds__(128) void k_bn_final(const float* __restrict__ g,
                                                  const float* __restrict__ b,
                                                  float invc)
{
    int d = threadIdx.x;
    float s = g_stats[d], sq = g_stats[128 + d];
    float mean = s * invc;
    float var = sq * invc - mean * mean;
    float sc = g[d] * rsqrtf(var + EPS_BN);
    g_bn_scale[d] = sc;
    g_bn_shift[d] = b[d] - mean * sc;
    g_stats[d] = 0.f;
    g_stats[128 + d] = 0.f;
}

// ---------------- node GEMM: Ah,Bh,Dh,Eh = h @ W.T + b ----------------
__global__ __launch_bounds__(512, 2) void k_node_gemm(
    int lay,
    const float* __restrict__ Ba, const float* __restrict__ Bb_,
    const float* __restrict__ Bd, const float* __restrict__ Be)
{
    const float* Bp[4] = {Ba, Bb_, Bd, Be};
    float* Op[4] = {g_Ah, g_Bh, g_Dh, g_Eh};
    extern __shared__ char smc[];
    half* ahi = (half*)smc;
    half* alo = ahi + 128 * SBF;
    half* whi = alo + 128 * SBF;

    int tid = threadIdx.x;
    int lane = tid & 31, w = tid >> 5;
    int m0w = (w & 3) * 32, n0w = (w >> 2) * 32;
    int n0 = blockIdx.x * 128;
    int mlim = N_NODES - n0;
    if (mlim > 128) mlim = 128;

    split_tileA(g_h + (size_t)n0 * 128, mlim, ahi, alo, tid);

    for (int mat = 0; mat < 4; mat++) {
        __syncthreads();
        const uint2* wsrc = (const uint2*)(g_Whi + (size_t)(lay * 5 + mat) * 128 * SBF);
        for (int i = tid; i < (128 * SBF) / 4; i += 512) ((uint2*)whi)[i] = wsrc[i];
        __syncthreads();
        float acc[2][4][4];
#pragma unroll
        for (int ms = 0; ms < 2; ms++)
#pragma unroll
            for (int nt = 0; nt < 4; nt++)
#pragma unroll
                for (int j = 0; j < 4; j++) acc[ms][nt][j] = 0.f;

        mma_mainloop(ahi, alo, whi, m0w, n0w, lane, acc);

        float* Out = Op[mat];
        const float* Bias = Bp[mat];
#pragma unroll
        for (int ms = 0; ms < 2; ms++)
#pragma unroll
            for (int nt = 0; nt < 4; nt++) {
                int col = n0w + nt * 8 + (lane & 3) * 2;
                float2 bv = *(const float2*)(Bias + col);
                int r0 = m0w + ms * 16 + (lane >> 2);
                if (r0 < mlim) {
                    float2 v = {acc[ms][nt][0] + bv.x, acc[ms][nt][1] + bv.y};
                    *(float2*)(Out + (size_t)(n0 + r0) * 128 + col) = v;
                }
                if (r0 + 8 < mlim) {
                    float2 v = {acc[ms][nt][2] + bv.x, acc[ms][nt][3] + bv.y};
                    *(float2*)(Out + (size_t)(n0 + r0 + 8) * 128 + col) = v;
                }
            }
    }
}

// ---------------- edge pass1: ehat = e@Cw.T + Cb + Dh[dst] + Eh[src]; BN stats --------
// lay==0: e tile computed from sim/len/ee_w/ee_b (g_e never read)
__global__ __launch_bounds__(512, 2) void k_edge_pass1(int lay,
                                                       const float* __restrict__ Cb,
                                                       const int* __restrict__ src,
                                                       const int* __restrict__ dst,
                                                       const float* __restrict__ sim,
                                                       const float* __restrict__ len,
                                                       const float* __restrict__ ew,
                                                       const float* __restrict__ eb)
{
    extern __shared__ char smc[];
    half* ahi = (half*)smc;
    half* alo = ahi + 128 * SBF;
    half* whi = alo + 128 * SBF;
    float* Csm = (float*)smc;                     // aliases ahi/alo after mma
    char* tail = smc + 3 * 128 * SBF * 2;
    int* s_src = (int*)tail;
    int* s_dst = s_src + 128;
    float* ssum = (float*)(s_dst + 128);
    float* ssq = ssum + 128;
    float* ssim = ssq + 128;
    float* slen = ssim + 128;
    float* sw0 = slen + 128;
    float* sw1 = sw0 + 128;
    float* sb = sw1 + 128;

    int tid = threadIdx.x;
    int lane = tid & 31, w = tid >> 5;
    int m0w = (w & 3) * 32, n0w = (w >> 2) * 32;
    int e0 = blockIdx.x * 128;

    if (tid < 128) {
        s_src[tid] = src[e0 + tid];
        s_dst[tid] = dst[e0 + tid];
        ssum[tid] = 0.f;
        ssq[tid] = 0.f;
    }
    if (lay == 0) {
        if (tid < 128) {
            ssim[tid] = sim[e0 + tid];
            slen[tid] = len[e0 + tid];
            sw0[tid] = ew[tid * 2];
            sw1[tid] = ew[tid * 2 + 1];
            sb[tid] = eb[tid];
        }
        __syncthreads();
#pragma unroll
        for (int i = tid; i < 128 * 32; i += 512) {
            int r = i >> 5, c = (i & 31) << 2;
            float s_ = ssim[r], l_ = slen[r];
            float4 v;
            v.x = fmaf(s_, sw0[c + 0], fmaf(l_, sw1[c + 0], sb[c + 0]));
            v.y = fmaf(s_, sw0[c + 1], fmaf(l_, sw1[c + 1], sb[c + 1]));
            v.z = fmaf(s_, sw0[c + 2], fmaf(l_, sw1[c + 2], sb[c + 2]));
            v.w = fmaf(s_, sw0[c + 3], fmaf(l_, sw1[c + 3], sb[c + 3]));
            split_store(ahi, alo, r * SBF + c, v);
        }
    } else {
        split_tileA(g_e + (size_t)e0 * 128, 128, ahi, alo, tid);
    }
    {
        const uint2* wsrc = (const uint2*)(g_Whi + (size_t)(lay * 5 + 4) * 128 * SBF);
        for (int i = tid; i < (128 * SBF) / 4; i += 512) ((uint2*)whi)[i] = wsrc[i];
    }
    __syncthreads();

    float acc[2][4][4];
#pragma unroll
    for (int ms = 0; ms < 2; ms++)
#pragma unroll
        for (int nt = 0; nt < 4; nt++)
#pragma unroll
            for (int j = 0; j < 4; j++) acc[ms][nt][j] = 0.f;

    mma_mainloop(ahi, alo, whi, m0w, n0w, lane, acc);

    __syncthreads();      // A tiles dead; Csm aliases them
#pragma unroll
    for (int ms = 0; ms < 2; ms++)
#pragma unroll
        for (int nt = 0; nt < 4; nt++) {
            int col = n0w + nt * 8 + (lane & 3) * 2;
            int r0 = m0w + ms * 16 + (lane >> 2);
            *(float2*)(Csm + r0 * SCF + col) = make_float2(acc[ms][nt][0], acc[ms][nt][1]);
            *(float2*)(Csm + (r0 + 8) * SCF + col) = make_float2(acc[ms][nt][2], acc[ms][nt][3]);
        }
    __syncthreads();

    // add Cb + Dh[dst] + Eh[src] in Csm (16 warps x 8 rows), accumulate stats
    int colg = (tid & 31) << 2;
    int r0 = (tid >> 5) << 3;
    float4 cb4 = *(const float4*)(Cb + colg);
    float s0 = 0.f, s1 = 0.f, s2 = 0.f, s3 = 0.f;
    float q0 = 0.f, q1 = 0.f, q2 = 0.f, q3 = 0.f;
#pragma unroll
    for (int j = 0; j < 8; j++) {
        int r = r0 + j;
        float* crow = Csm + r * SCF + colg;
        float4 c = *(const float4*)crow;
        int dd = s_dst[r], sr = s_src[r];
        float4 dh = *(const float4*)(g_Dh + (size_t)dd * 128 + colg);
        float4 eh = *(const float4*)(g_Eh + (size_t)sr * 128 + colg);
        float4 v;
        v.x = c.x + cb4.x + dh.x + eh.x;
        v.y = c.y + cb4.y + dh.y + eh.y;
        v.z = c.z + cb4.z + dh.z + eh.z;
        v.w = c.w + cb4.w + dh.w + eh.w;
        *(float4*)crow = v;
        s0 += v.x; q0 += v.x * v.x;
        s1 += v.y; q1 += v.y * v.y;
        s2 += v.z; q2 += v.z * v.z;
        s3 += v.w; q3 += v.w * v.w;
    }
    atomicAdd(&ssum[colg + 0], s0); atomicAdd(&ssq[colg + 0], q0);
    atomicAdd(&ssum[colg + 1], s1); atomicAdd(&ssq[colg + 1], q1);
    atomicAdd(&ssum[colg + 2], s2); atomicAdd(&ssq[colg + 2], q2);
    atomicAdd(&ssum[colg + 3], s3); atomicAdd(&ssq[colg + 3], q3);
    __syncthreads();

    // coalesced fp16 ehat store
    for (int i = tid; i < 128 * 32; i += 512) {
        int r = i >> 5, c4 = (i & 31) << 2;
        float4 v = *(const float4*)(Csm + r * SCF + c4);
        half2 p0 = __floats2half2_rn(v.x, v.y);
        half2 p1 = __floats2half2_rn(v.z, v.w);
        *(uint2*)(g_ehat + (size_t)(e0 + r) * 128 + c4) =
            make_uint2(*(unsigned*)&p0, *(unsigned*)&p1);
    }
    if (tid < 128) {
        atomicAdd(&g_stats[tid], ssum[tid]);
        atomicAdd(&g_stats[128 + tid], ssq[tid]);
    }
}

// ---------------- fused agg: 8 nodes/block ----------------
// e update (lay0: e = e0 + relu, else e += relu), aggregation, t + stats
__global__ __launch_bounds__(128) void k_agg_fused(const int* __restrict__ src,
                                                   const float* __restrict__ sim,
                                                   const float* __restrict__ len,
                                                   const float* __restrict__ ew,
                                                   const float* __restrict__ eb,
                                                   int lay)
{
    int d = threadIdx.x;
    int n0 = blockIdx.x * 8;
    float sc = g_bn_scale[d], sh = g_bn_shift[d];
    float w0 = 0.f, w1 = 0.f, b0 = 0.f;
    if (lay == 0) {
        w0 = ew[d * 2];
        w1 = ew[d * 2 + 1];
        b0 = eb[d];
    }
    float ts = 0.f, tq = 0.f;
#pragma unroll 1
    for (int k = 0; k < 8; k++) {
        int n = n0 + k;
        int beg = g_off[n], end = g_off[n + 1];
        float num = 0.f, den = 0.f;
        for (int j = beg; j < end; j++) {
            int eid = g_eids[j];
            float x = __half2float(g_ehat[(size_t)eid * 128 + d]);
            float s = 1.f / (1.f + __expf(-x));
            num += s * g_Bh[(size_t)src[eid] * 128 + d];
            den += s;
            float rel = fmaxf(fmaf(x, sc, sh), 0.f);
            if (lay == 0) {
                float e0v = fmaf(sim[eid], w0, fmaf(len[eid], w1, b0));
                g_e[(size_t)eid * 128 + d] = e0v + rel;
            } else {
                g_e[(size_t)eid * 128 + d] += rel;
            }
        }
        float t = g_Ah[n * 128 + d] + num / (den + EPS_AGG);
        g_t[n * 128 + d] = t;
        ts += t;
        tq += t * t;
    }
    atomicAdd(&g_stats[d], ts);
    atomicAdd(&g_stats[128 + d], tq);
}

// ---------------- h += relu(bn(t)) ----------------
__global__ __launch_bounds__(256) void k_node_update()
{
    int i = blockIdx.x * 256 + threadIdx.x;
    int d4 = (i & 31) << 2;
    float4 sc = *(const float4*)(g_bn_scale + d4);
    float4 sh = *(const float4*)(g_bn_shift + d4);
    float4 x = ((const float4*)g_t)[i];
    float4 hv = ((const float4*)g_h)[i];
    hv.x += fmaxf(fmaf(x.x, sc.x, sh.x), 0.f);
    hv.y += fmaxf(fmaf(x.y, sc.y, sh.y), 0.f);
    hv.z += fmaxf(fmaf(x.z, sc.z, sh.z), 0.f);
    hv.w += fmaxf(fmaf(x.w, sc.w, sh.w), 0.f);
    ((float4*)g_h)[i] = hv;
}

// ---------------- decoder ----------------
__global__ __launch_bounds__(256) void k_dec(const float* __restrict__ dw,
                                             const float* __restrict__ db,
                                             const int* __restrict__ src,
                                             const int* __restrict__ dst,
                                             float* __restrict__ out)
{
    int w = (blockIdx.x * 256 + threadIdx.x) >> 5;
    if (w >= N_EDGES) return;
    int lane = threadIdx.x & 31;
    int s = src[w], d = dst[w];
    float4 w1 = *(const float4*)(dw + lane * 4);
    float4 w2 = *(const float4*)(dw + 128 + lane * 4);
    float4 w3 = *(const float4*)(dw + 256 + lane * 4);
    float4 hs = *(const float4*)(g_h + (size_t)s * 128 + lane * 4);
    float4 hd = *(const float4*)(g_h + (size_t)d * 128 + lane * 4);
    float4 ee = *(const float4*)(g_e + (size_t)w * 128 + lane * 4);
    float acc = w1.x * hs.x + w1.y * hs.y + w1.z * hs.z + w1.w * hs.w
              + w2.x * hd.x + w2.y * hd.y + w2.z * hd.z + w2.w * hd.w
              + w3.x * ee.x + w3.y * ee.y + w3.z * ee.z + w3.w * ee.w;
#pragma unroll
    for (int ofs = 16; ofs > 0; ofs >>= 1) acc += __shfl_down_sync(0xffffffffu, acc, ofs);
    if (lane == 0) out[w] = acc + db[0];
}

// ---------------- launcher ----------------
extern "C" void kernel_launch(void* const* d_in, const int* in_sizes, int n_in,
                              void* d_out, int out_size)
{
    const float* emb    = (const float*)d_in[0];
    const float* conv_w = (const float*)d_in[1];
    const float* conv_b = (const float*)d_in[2];
    const float* ee_w   = (const float*)d_in[3];
    const float* ee_b   = (const float*)d_in[4];
    const float* Aw     = (const float*)d_in[5];
    const float* Ab     = (const float*)d_in[6];
    const float* Bw     = (const float*)d_in[7];
    const float* Bb     = (const float*)d_in[8];
    const float* Cw     = (const float*)d_in[9];
    const float* Cb     = (const float*)d_in[10];
    const float* Dw     = (const float*)d_in[11];
    const float* Db     = (const float*)d_in[12];
    const float* Ew     = (const float*)d_in[13];
    const float* Eb     = (const float*)d_in[14];
    const float* bnh_g  = (const float*)d_in[15];
    const float* bnh_b  = (const float*)d_in[16];
    const float* bne_g  = (const float*)d_in[17];
    const float* bne_b  = (const float*)d_in[18];
    const float* dec_w  = (const float*)d_in[19];
    const float* dec_b  = (const float*)d_in[20];
    const float* sim    = (const float*)d_in[21];
    const float* length = (const float*)d_in[22];
    const int*   reads  = (const int*)d_in[23];
    const int*   src    = (const int*)d_in[24];
    const int*   dst    = (const int*)d_in[25];
    float* out = (float*)d_out;

    const int smemG = 3 * 128 * SBF * 2;                  // 104448 -> 2 blocks/SM
    const int smemE = smemG + 9 * 128 * 4;                 // 109056 -> 2 blocks/SM
    const int smemS = (10 * 16 * DIM) * 4 + 2 * 512 * 4;   // 86016
    cudaFuncSetAttribute(k_node_gemm, cudaFuncAttributeMaxDynamicSharedMemorySize, smemG);
    cudaFuncSetAttribute(k_edge_pass1, cudaFuncAttributeMaxDynamicSharedMemorySize, smemE);
    cudaFuncSetAttribute(k_seq, cudaFuncAttributeMaxDynamicSharedMemorySize, smemS);

    const float invE = 1.f / (float)N_EDGES;
    const float invN = 1.f / (float)N_NODES;

    k_wsum<<<40, 256>>>(emb, conv_w);                                   // 0
    k_wsplit<<<20, 256>>>(Aw, Bw, Cw, Dw, Ew);                          // 1
    k_W2<<<(10 * 16 * DIM + 255) / 256, 256>>>();                       // 2
    k_seq<<<N_NODES / 8, 512, smemS>>>(reads, conv_b);                  // 3 <- profiled
    k_node_gemm<<<(N_NODES + 127) / 128, 512, smemG>>>(                 // 4
        0, Ab, Bb, Db, Eb);
    k_edge_pass1<<<N_EDGES / 128, 512, smemE>>>(                        // 5
        0, Cb, src, dst, sim, length, ee_w, ee_b);

    k_csr_zero<<<(N_NODES + 255) / 256, 256>>>();
    k_hist<<<N_EDGES / 256, 256>>>(dst);
    k_scan<<<1, 1024>>>();
    k_scatter<<<N_EDGES / 256, 256>>>(dst);

    k_bn_final<<<1, 128>>>(bne_g, bne_b, invE);
    k_agg_fused<<<N_NODES / 8, 128>>>(src, sim, length, ee_w, ee_b, 0);
    k_bn_final<<<1, 128>>>(bnh_g, bnh_b, invN);
    k_node_update<<<(N_NODES * 32) / 256, 256>>>();

    for (int i = 1; i < N_LAYERS; i++) {
        const int bo = i * DIM;
        k_node_gemm<<<(N_NODES + 127) / 128, 512, smemG>>>(
            i, Ab + bo, Bb + bo, Db + bo, Eb + bo);
        k_edge_pass1<<<N_EDGES / 128, 512, smemE>>>(
            i, Cb + bo, src, dst, sim, length, ee_w, ee_b);
        k_bn_final<<<1, 128>>>(bne_g + bo, bne_b + bo, invE);
        k_agg_fused<<<N_NODES / 8, 128>>>(src, sim, length, ee_w, ee_b, i);
        k_bn_final<<<1, 128>>>(bnh_g + bo, bnh_b + bo, invN);
        k_node_update<<<(N_NODES * 32) / 256, 256>>>();
    }
    k_dec<<<(N_EDGES * 32 + 255) / 256, 256>>>(dec_w, dec_b, src, dst, out);
}

// round 12
// speedup vs baseline: 1.1738x; 1.1738x over previous
#include <cuda_runtime.h>
#include <cuda_fp16.h>
#include <cstdint>

#define N_NODES 20000
#define READ_LEN 64
#define N_EDGES 320000
#define DIM 128
#define KSZ 20
#define CONV_T (READ_LEN - KSZ + 1)
#define N_LAYERS 4
#define EPS_BN 1e-5f
#define EPS_AGG 1e-6f

#define SBF 136   // half smem row stride (272B): 16B-aligned rows, ldsm conflict-free
#define SCF 132   // fp32 C smem row stride

// ---------------- device scratch ----------------
__device__ float g_h[N_NODES * DIM];
__device__ float g_e[(size_t)N_EDGES * DIM];
__device__ half  g_ehat[(size_t)N_EDGES * DIM];      // fp16 ehat
__device__ float g_Ah[N_NODES * DIM];
__device__ float g_Bh[N_NODES * DIM];
__device__ float g_Dh[N_NODES * DIM];
__device__ float g_Eh[N_NODES * DIM];
__device__ float g_t[N_NODES * DIM];
__device__ float g_wsum[4 * KSZ * DIM];
__device__ float g_W2[10 * 16 * DIM];
__device__ half  g_Whi[20 * 128 * SBF];              // pre-split weights (smem image)
__device__ float g_stats[2 * DIM];                   // zero-init; bn_final restores zeros
__device__ float g_bn_scale[DIM];
__device__ float g_bn_shift[DIM];
__device__ int g_cnt[N_NODES];
__device__ int g_off[N_NODES + 1];
__device__ int g_cur[N_NODES];
__device__ int g_eids[N_EDGES];

// ---------------- mma helpers ----------------
__device__ __forceinline__ unsigned s2u(const void* p)
{
    return (unsigned)__cvta_generic_to_shared(p);
}
__device__ __forceinline__ void ldsm4(unsigned* r, unsigned addr)
{
    asm volatile("ldmatrix.sync.aligned.m8n8.x4.shared.b16 {%0,%1,%2,%3}, [%4];"
                 : "=r"(r[0]), "=r"(r[1]), "=r"(r[2]), "=r"(r[3]) : "r"(addr));
}
__device__ __forceinline__ void mma16816(float* c, const unsigned* a, const unsigned* b)
{
    asm volatile("mma.sync.aligned.m16n8k16.row.col.f32.f16.f16.f32 "
                 "{%0,%1,%2,%3}, {%4,%5,%6,%7}, {%8,%9}, {%0,%1,%2,%3};"
                 : "+f"(c[0]), "+f"(c[1]), "+f"(c[2]), "+f"(c[3])
                 : "r"(a[0]), "r"(a[1]), "r"(a[2]), "r"(a[3]), "r"(b[0]), "r"(b[1]));
}

// pack 4 fp32 into hi/lo fp16 pairs and store to smem tile offset
__device__ __forceinline__ void split_store(half* hi, half* lo, int off4, float4 v)
{
    half hx = __float2half_rn(v.x), hy = __float2half_rn(v.y);
    half hz = __float2half_rn(v.z), hw = __float2half_rn(v.w);
    half2 hp0 = __halves2half2(hx, hy), hp1 = __halves2half2(hz, hw);
    half2 lp0 = __floats2half2_rn(v.x - __half2float(hx), v.y - __half2float(hy));
    half2 lp1 = __floats2half2_rn(v.z - __half2float(hz), v.w - __half2float(hw));
    *(uint2*)(hi + off4) = make_uint2(*(unsigned*)&hp0, *(unsigned*)&hp1);
    *(uint2*)(lo + off4) = make_uint2(*(unsigned*)&lp0, *(unsigned*)&lp1);
}

// split fp32 tile [rows<=128][128] into hi/lo fp16 smem tiles (512 threads)
__device__ __forceinline__ void split_tileA(const float* __restrict__ g, int rows,
                                            half* hi, half* lo, int tid)
{
#pragma unroll
    for (int i = tid; i < 128 * 32; i += 512) {
        int r = i >> 5, c = (i & 31) << 2;
        float4 v = make_float4(0.f, 0.f, 0.f, 0.f);
        if (r < rows) v = *(const float4*)(g + r * 128 + c);
        split_store(hi, lo, r * SBF + c, v);
    }
}

// mainloop (per warp, 32x32 tile): acc += Ahi*Whi + Alo*Whi; A frags reused (regs<=64)
__device__ __forceinline__ void mma_mainloop(const half* ahi, const half* alo,
                                             const half* whi,
                                             int m0w, int n0w, int lane,
                                             float acc[2][4][4])
{
    int aoff = (lane & 15) * SBF + (lane >> 4) * 8;
    int boff = ((lane & 7) + ((lane >> 4) << 3)) * SBF + ((lane >> 3) & 1) * 8;
#pragma unroll
    for (int kt = 0; kt < 8; kt++) {
        unsigned bf[2][4];
#pragma unroll
        for (int np = 0; np < 2; np++) {
            int o = (n0w + np * 16) * SBF + boff + kt * 16;
            ldsm4(bf[np], s2u(whi + o));
        }
        unsigned af[2][4];
#pragma unroll
        for (int ms = 0; ms < 2; ms++) {
            int o = (m0w + ms * 16) * SBF + aoff + kt * 16;
            ldsm4(af[ms], s2u(ahi + o));
        }
#pragma unroll
        for (int ms = 0; ms < 2; ms++)
#pragma unroll
            for (int nt = 0; nt < 4; nt++)
                mma16816(acc[ms][nt], af[ms], &bf[nt >> 1][(nt & 1) * 2]);
#pragma unroll
        for (int ms = 0; ms < 2; ms++) {
            int o = (m0w + ms * 16) * SBF + aoff + kt * 16;
            ldsm4(af[ms], s2u(alo + o));      // overwrite hi frags
        }
#pragma unroll
        for (int ms = 0; ms < 2; ms++)
#pragma unroll
            for (int nt = 0; nt < 4; nt++)
                mma16816(acc[ms][nt], af[ms], &bf[nt >> 1][(nt & 1) * 2]);
    }
}

// ---------------- prep ----------------
__global__ void k_wsum(const float* __restrict__ emb, const float* __restrict__ cw)
{
    int idx = blockIdx.x * 256 + threadIdx.x;
    if (idx >= 4 * KSZ * DIM) return;
    int d = idx & 127;
    int bk = idx >> 7;
    int k = bk % KSZ, b = bk / KSZ;
    float s = 0.f;
#pragma unroll
    for (int c = 0; c < 3; c++) s += emb[b * 3 + c] * cw[d * 3 * KSZ + c * KSZ + k];
    g_wsum[idx] = s;
}

__global__ void k_wsplit(const float* __restrict__ Aw, const float* __restrict__ Bw,
                         const float* __restrict__ Cw, const float* __restrict__ Dw,
                         const float* __restrict__ Ew)
{
    int m = blockIdx.x, tid = threadIdx.x;   // 20 blocks
    int lay = m / 5, which = m % 5;
    const float* srcs[5] = {Aw, Bw, Dw, Ew, Cw};
    const float* src = srcs[which] + lay * DIM * DIM;
    half* dst = g_Whi + (size_t)m * 128 * SBF;
    for (int i = tid; i < 128 * 128; i += 256) {
        int r = i >> 7, c = i & 127;
        dst[r * SBF + c] = __float2half_rn(src[i]);
    }
}

__global__ void k_W2()
{
    int idx = blockIdx.x * 256 + threadIdx.x;
    if (idx >= 10 * 16 * DIM) return;
    int d = idx & 127;
    int r = idx >> 7;
    int c2 = r & 15, k2 = r >> 4;
    int a = c2 >> 2, b = c2 & 3;
    g_W2[idx] = g_wsum[(a * KSZ + 2 * k2) * DIM + d] + g_wsum[(b * KSZ + 2 * k2 + 1) * DIM + d];
}

__global__ __launch_bounds__(512) void k_seq(const int* __restrict__ reads,
                                             const float* __restrict__ conv_b)
{
    extern __shared__ float sm[];
    float* sW2 = sm;
    int* scode = (int*)(sm + 10 * 16 * DIM);
    int* spc = scode + 512;
    int tid = threadIdx.x;

    for (int i = tid; i < (10 * 16 * DIM) / 4; i += 512)
        ((float4*)sW2)[i] = ((const float4*)g_W2)[i];

    int nl = tid >> 6, l = tid & 63;
    int n = blockIdx.x * 8 + nl;
    scode[tid] = reads[n * READ_LEN + l];
    __syncthreads();
    if (l < 63) spc[tid] = (scode[tid] * 4 + scode[tid + 1]) << 7;
    __syncthreads();

    int dp = tid & 63;
    const float* wd = sW2 + dp * 2;
    const int* pc = spc + nl * 64;
    float m0 = -3.4e38f, m1 = -3.4e38f;
#pragma unroll
    for (int t = 0; t < CONV_T; t++) {
        float s0 = 0.f, s1 = 0.f;
#pragma unroll
        for (int k2 = 0; k2 < 10; k2++) {
            float2 v = *(const float2*)(wd + pc[t + 2 * k2] + k2 * 2048);
            s0 += v.x; s1 += v.y;
        }
        m0 = fmaxf(m0, s0);
        m1 = fmaxf(m1, s1);
    }
    float2 bv = *(const float2*)(conv_b + dp * 2);
    float2 hv;
    hv.x = fmaxf(m0 + bv.x, 0.f);
    hv.y = fmaxf(m1 + bv.y, 0.f);
    *(float2*)(g_h + n * DIM + dp * 2) = hv;
}

// ---------------- CSR build by dst ----------------
__global__ void k_csr_zero()
{
    int i = blockIdx.x * 256 + threadIdx.x;
    if (i < N_NODES) g_cnt[i] = 0;
}
__global__ void k_hist(const int* __restrict__ dst)
{
    int i = blockIdx.x * 256 + threadIdx.x;
    if (i < N_EDGES) atomicAdd(&g_cnt[dst[i]], 1);
}
__global__ __launch_bounds__(1024) void k_scan()
{
    __shared__ int sd[1024];
    int tid = threadIdx.x;
    int carry = 0;
    for (int base = 0; base < N_NODES; base += 1024) {
        int i = base + tid;
        int v = (i < N_NODES) ? g_cnt[i] : 0;
        __syncthreads();
        sd[tid] = v;
        __syncthreads();
        for (int ofs = 1; ofs < 1024; ofs <<= 1) {
            int t = (tid >= ofs) ? sd[tid - ofs] : 0;
            __syncthreads();
            sd[tid] += t;
            __syncthreads();
        }
        if (i < N_NODES) {
            int ex = carry + sd[tid] - v;
            g_off[i] = ex;
            g_cur[i] = ex;
        }
        carry += sd[1023];
    }
    if (tid == 0) g_off[N_NODES] = carry;
}
__global__ void k_scatter(const int* __restrict__ dst)
{
    int i = blockIdx.x * 256 + threadIdx.x;
    if (i < N_EDGES) {
        int p = atomicAdd(&g_cur[dst[i]], 1);
        g_eids[p] = i;
    }
}

// ---------------- BN finalize (restores g_stats zero invariant) ----------------
__global__ __launch_bounds__(128) void k_bn_final(const float* __restrict__ g,
                                                  const float* __restrict__ b,
                                                  float invc)
{
    int d = threadIdx.x;
    float s = g_stats[d], sq = g_stats[128 + d];
    float mean = s * invc;
    float var = sq * invc - mean * mean;
    float sc = g[d] * rsqrtf(var + EPS_BN);
    g_bn_scale[d] = sc;
    g_bn_shift[d] = b[d] - mean * sc;
    g_stats[d] = 0.f;
    g_stats[128 + d] = 0.f;
}

// ---------------- node GEMM: Ah,Bh,Dh,Eh = h @ W.T + b ----------------
__global__ __launch_bounds__(512, 2) void k_node_gemm(
    int lay,
    const float* __restrict__ Ba, const float* __restrict__ Bb_,
    const float* __restrict__ Bd, const float* __restrict__ Be)
{
    const float* Bp[4] = {Ba, Bb_, Bd, Be};
    float* Op[4] = {g_Ah, g_Bh, g_Dh, g_Eh};
    extern __shared__ char smc[];
    half* ahi = (half*)smc;
    half* alo = ahi + 128 * SBF;
    half* whi = alo + 128 * SBF;

    int tid = threadIdx.x;
    int lane = tid & 31, w = tid >> 5;
    int m0w = (w & 3) * 32, n0w = (w >> 2) * 32;
    int n0 = blockIdx.x * 128;
    int mlim = N_NODES - n0;
    if (mlim > 128) mlim = 128;

    split_tileA(g_h + (size_t)n0 * 128, mlim, ahi, alo, tid);

    for (int mat = 0; mat < 4; mat++) {
        __syncthreads();
        const uint2* wsrc = (const uint2*)(g_Whi + (size_t)(lay * 5 + mat) * 128 * SBF);
        for (int i = tid; i < (128 * SBF) / 4; i += 512) ((uint2*)whi)[i] = wsrc[i];
        __syncthreads();
        float acc[2][4][4];
#pragma unroll
        for (int ms = 0; ms < 2; ms++)
#pragma unroll
            for (int nt = 0; nt < 4; nt++)
#pragma unroll
                for (int j = 0; j < 4; j++) acc[ms][nt][j] = 0.f;

        mma_mainloop(ahi, alo, whi, m0w, n0w, lane, acc);

        float* Out = Op[mat];
        const float* Bias = Bp[mat];
#pragma unroll
        for (int ms = 0; ms < 2; ms++)
#pragma unroll
            for (int nt = 0; nt < 4; nt++) {
                int col = n0w + nt * 8 + (lane & 3) * 2;
                float2 bv = *(const float2*)(Bias + col);
                int r0 = m0w + ms * 16 + (lane >> 2);
                if (r0 < mlim) {
                    float2 v = {acc[ms][nt][0] + bv.x, acc[ms][nt][1] + bv.y};
                    *(float2*)(Out + (size_t)(n0 + r0) * 128 + col) = v;
                }
                if (r0 + 8 < mlim) {
                    float2 v = {acc[ms][nt][2] + bv.x, acc[ms][nt][3] + bv.y};
                    *(float2*)(Out + (size_t)(n0 + r0 + 8) * 128 + col) = v;
                }
            }
    }
}

// ---------------- edge pass1: ehat = e@Cw.T + Cb + Dh[dst] + Eh[src]; BN stats --------
// lay==0: e tile computed from sim/len/ee_w/ee_b (g_e never read)
__global__ __launch_bounds__(512, 2) void k_edge_pass1(int lay,
                                                       const float* __restrict__ Cb,
                                                       const int* __restrict__ src,
                                                       const int* __restrict__ dst,
                                                       const float* __restrict__ sim,
                                                       const float* __restrict__ len,
                                                       const float* __restrict__ ew,
                                                       const float* __restrict__ eb)
{
    extern __shared__ char smc[];
    half* ahi = (half*)smc;
    half* alo = ahi + 128 * SBF;
    half* whi = alo + 128 * SBF;
    float* Csm = (float*)smc;                     // aliases ahi/alo after mma
    char* tail = smc + 3 * 128 * SBF * 2;
    int* s_src = (int*)tail;
    int* s_dst = s_src + 128;
    float* ssum = (float*)(s_dst + 128);
    float* ssq = ssum + 128;
    float* ssim = ssq + 128;
    float* slen = ssim + 128;
    float* sw0 = slen + 128;
    float* sw1 = sw0 + 128;
    float* sb = sw1 + 128;

    int tid = threadIdx.x;
    int lane = tid & 31, w = tid >> 5;
    int m0w = (w & 3) * 32, n0w = (w >> 2) * 32;
    int e0 = blockIdx.x * 128;

    if (tid < 128) {
        s_src[tid] = src[e0 + tid];
        s_dst[tid] = dst[e0 + tid];
        ssum[tid] = 0.f;
        ssq[tid] = 0.f;
    }
    if (lay == 0) {
        if (tid < 128) {
            ssim[tid] = sim[e0 + tid];
            slen[tid] = len[e0 + tid];
            sw0[tid] = ew[tid * 2];
            sw1[tid] = ew[tid * 2 + 1];
            sb[tid] = eb[tid];
        }
        __syncthreads();
#pragma unroll
        for (int i = tid; i < 128 * 32; i += 512) {
            int r = i >> 5, c = (i & 31) << 2;
            float s_ = ssim[r], l_ = slen[r];
            float4 v;
            v.x = fmaf(s_, sw0[c + 0], fmaf(l_, sw1[c + 0], sb[c + 0]));
            v.y = fmaf(s_, sw0[c + 1], fmaf(l_, sw1[c + 1], sb[c + 1]));
            v.z = fmaf(s_, sw0[c + 2], fmaf(l_, sw1[c + 2], sb[c + 2]));
            v.w = fmaf(s_, sw0[c + 3], fmaf(l_, sw1[c + 3], sb[c + 3]));
            split_store(ahi, alo, r * SBF + c, v);
        }
    } else {
        split_tileA(g_e + (size_t)e0 * 128, 128, ahi, alo, tid);
    }
    {
        const uint2* wsrc = (const uint2*)(g_Whi + (size_t)(lay * 5 + 4) * 128 * SBF);
        for (int i = tid; i < (128 * SBF) / 4; i += 512) ((uint2*)whi)[i] = wsrc[i];
    }
    __syncthreads();

    float acc[2][4][4];
#pragma unroll
    for (int ms = 0; ms < 2; ms++)
#pragma unroll
        for (int nt = 0; nt < 4; nt++)
#pragma unroll
            for (int j = 0; j < 4; j++) acc[ms][nt][j] = 0.f;

    mma_mainloop(ahi, alo, whi, m0w, n0w, lane, acc);

    __syncthreads();      // A tiles dead; Csm aliases them
#pragma unroll
    for (int ms = 0; ms < 2; ms++)
#pragma unroll
        for (int nt = 0; nt < 4; nt++) {
            int col = n0w + nt * 8 + (lane & 3) * 2;
            int r0 = m0w + ms * 16 + (lane >> 2);
            *(float2*)(Csm + r0 * SCF + col) = make_float2(acc[ms][nt][0], acc[ms][nt][1]);
            *(float2*)(Csm + (r0 + 8) * SCF + col) = make_float2(acc[ms][nt][2], acc[ms][nt][3]);
        }
    __syncthreads();

    // add Cb + Dh[dst] + Eh[src] in Csm (16 warps x 8 rows), accumulate stats
    int colg = (tid & 31) << 2;
    int r0 = (tid >> 5) << 3;
    float4 cb4 = *(const float4*)(Cb + colg);
    float s0 = 0.f, s1 = 0.f, s2 = 0.f, s3 = 0.f;
    float q0 = 0.f, q1 = 0.f, q2 = 0.f, q3 = 0.f;
#pragma unroll
    for (int j = 0; j < 8; j++) {
        int r = r0 + j;
        float* crow = Csm + r * SCF + colg;
        float4 c = *(const float4*)crow;
        int dd = s_dst[r], sr = s_src[r];
        float4 dh = *(const float4*)(g_Dh + (size_t)dd * 128 + colg);
        float4 eh = *(const float4*)(g_Eh + (size_t)sr * 128 + colg);
        float4 v;
        v.x = c.x + cb4.x + dh.x + eh.x;
        v.y = c.y + cb4.y + dh.y + eh.y;
        v.z = c.z + cb4.z + dh.z + eh.z;
        v.w = c.w + cb4.w + dh.w + eh.w;
        *(float4*)crow = v;
        s0 += v.x; q0 += v.x * v.x;
        s1 += v.y; q1 += v.y * v.y;
        s2 += v.z; q2 += v.z * v.z;
        s3 += v.w; q3 += v.w * v.w;
    }
    atomicAdd(&ssum[colg + 0], s0); atomicAdd(&ssq[colg + 0], q0);
    atomicAdd(&ssum[colg + 1], s1); atomicAdd(&ssq[colg + 1], q1);
    atomicAdd(&ssum[colg + 2], s2); atomicAdd(&ssq[colg + 2], q2);
    atomicAdd(&ssum[colg + 3], s3); atomicAdd(&ssq[colg + 3], q3);
    __syncthreads();

    // coalesced fp16 ehat store
    for (int i = tid; i < 128 * 32; i += 512) {
        int r = i >> 5, c4 = (i & 31) << 2;
        float4 v = *(const float4*)(Csm + r * SCF + c4);
        half2 p0 = __floats2half2_rn(v.x, v.y);
        half2 p1 = __floats2half2_rn(v.z, v.w);
        *(uint2*)(g_ehat + (size_t)(e0 + r) * 128 + c4) =
            make_uint2(*(unsigned*)&p0, *(unsigned*)&p1);
    }
    if (tid < 128) {
        atomicAdd(&g_stats[tid], ssum[tid]);
        atomicAdd(&g_stats[128 + tid], ssq[tid]);
    }
}

// ---------------- fused agg (1 node/block): e update + aggregation + t + stats ----------
__global__ __launch_bounds__(128) void k_agg_fused(const int* __restrict__ src,
                                                   const float* __restrict__ sim,
                                                   const float* __restrict__ len,
                                                   const float* __restrict__ ew,
                                                   const float* __restrict__ eb,
                                                   int lay)
{
    int n = blockIdx.x;
    int d = threadIdx.x;
    int beg = g_off[n], end = g_off[n + 1];
    float sc = g_bn_scale[d], sh = g_bn_shift[d];
    float w0 = 0.f, w1 = 0.f, b0 = 0.f;
    if (lay == 0) {
        w0 = ew[d * 2];
        w1 = ew[d * 2 + 1];
        b0 = eb[d];
    }
    float num = 0.f, den = 0.f;
    for (int j = beg; j < end; j++) {
        int eid = g_eids[j];
        float x = __half2float(g_ehat[(size_t)eid * 128 + d]);
        float s = 1.f / (1.f + __expf(-x));
        num += s * g_Bh[(size_t)src[eid] * 128 + d];
        den += s;
        float rel = fmaxf(fmaf(x, sc, sh), 0.f);
        if (lay == 0) {
            float e0v = fmaf(sim[eid], w0, fmaf(len[eid], w1, b0));
            g_e[(size_t)eid * 128 + d] = e0v + rel;
        } else {
            g_e[(size_t)eid * 128 + d] += rel;
        }
    }
    float t = g_Ah[n * 128 + d] + num / (den + EPS_AGG);
    g_t[n * 128 + d] = t;
    atomicAdd(&g_stats[d], t);
    atomicAdd(&g_stats[128 + d], t * t);
}

// ---------------- h += relu(bn(t)) ----------------
__global__ __launch_bounds__(256) void k_node_update()
{
    int i = blockIdx.x * 256 + threadIdx.x;
    int d4 = (i & 31) << 2;
    float4 sc = *(const float4*)(g_bn_scale + d4);
    float4 sh = *(const float4*)(g_bn_shift + d4);
    float4 x = ((const float4*)g_t)[i];
    float4 hv = ((const float4*)g_h)[i];
    hv.x += fmaxf(fmaf(x.x, sc.x, sh.x), 0.f);
    hv.y += fmaxf(fmaf(x.y, sc.y, sh.y), 0.f);
    hv.z += fmaxf(fmaf(x.z, sc.z, sh.z), 0.f);
    hv.w += fmaxf(fmaf(x.w, sc.w, sh.w), 0.f);
    ((float4*)g_h)[i] = hv;
}

// ---------------- decoder ----------------
__global__ __launch_bounds__(256) void k_dec(const float* __restrict__ dw,
                                             const float* __restrict__ db,
                                             const int* __restrict__ src,
                                             const int* __restrict__ dst,
                                             float* __restrict__ out)
{
    int w = (blockIdx.x * 256 + threadIdx.x) >> 5;
    if (w >= N_EDGES) return;
    int lane = threadIdx.x & 31;
    int s = src[w], d = dst[w];
    float4 w1 = *(const float4*)(dw + lane * 4);
    float4 w2 = *(const float4*)(dw + 128 + lane * 4);
    float4 w3 = *(const float4*)(dw + 256 + lane * 4);
    float4 hs = *(const float4*)(g_h + (size_t)s * 128 + lane * 4);
    float4 hd = *(const float4*)(g_h + (size_t)d * 128 + lane * 4);
    float4 ee = *(const float4*)(g_e + (size_t)w * 128 + lane * 4);
    float acc = w1.x * hs.x + w1.y * hs.y + w1.z * hs.z + w1.w * hs.w
              + w2.x * hd.x + w2.y * hd.y + w2.z * hd.z + w2.w * hd.w
              + w3.x * ee.x + w3.y * ee.y + w3.z * ee.z + w3.w * ee.w;
#pragma unroll
    for (int ofs = 16; ofs > 0; ofs >>= 1) acc += __shfl_down_sync(0xffffffffu, acc, ofs);
    if (lane == 0) out[w] = acc + db[0];
}

// ---------------- launcher ----------------
extern "C" void kernel_launch(void* const* d_in, const int* in_sizes, int n_in,
                              void* d_out, int out_size)
{
    const float* emb    = (const float*)d_in[0];
    const float* conv_w = (const float*)d_in[1];
    const float* conv_b = (const float*)d_in[2];
    const float* ee_w   = (const float*)d_in[3];
    const float* ee_b   = (const float*)d_in[4];
    const float* Aw     = (const float*)d_in[5];
    const float* Ab     = (const float*)d_in[6];
    const float* Bw     = (const float*)d_in[7];
    const float* Bb     = (const float*)d_in[8];
    const float* Cw     = (const float*)d_in[9];
    const float* Cb     = (const float*)d_in[10];
    const float* Dw     = (const float*)d_in[11];
    const float* Db     = (const float*)d_in[12];
    const float* Ew     = (const float*)d_in[13];
    const float* Eb     = (const float*)d_in[14];
    const float* bnh_g  = (const float*)d_in[15];
    const float* bnh_b  = (const float*)d_in[16];
    const float* bne_g  = (const float*)d_in[17];
    const float* bne_b  = (const float*)d_in[18];
    const float* dec_w  = (const float*)d_in[19];
    const float* dec_b  = (const float*)d_in[20];
    const float* sim    = (const float*)d_in[21];
    const float* length = (const float*)d_in[22];
    const int*   reads  = (const int*)d_in[23];
    const int*   src    = (const int*)d_in[24];
    const int*   dst    = (const int*)d_in[25];
    float* out = (float*)d_out;

    const int smemG = 3 * 128 * SBF * 2;                  // 104448 -> 2 blocks/SM
    const int smemE = smemG + 9 * 128 * 4;                 // 109056 -> 2 blocks/SM
    const int smemS = (10 * 16 * DIM) * 4 + 2 * 512 * 4;   // 86016
    cudaFuncSetAttribute(k_node_gemm, cudaFuncAttributeMaxDynamicSharedMemorySize, smemG);
    cudaFuncSetAttribute(k_edge_pass1, cudaFuncAttributeMaxDynamicSharedMemorySize, smemE);
    cudaFuncSetAttribute(k_seq, cudaFuncAttributeMaxDynamicSharedMemorySize, smemS);

    const float invE = 1.f / (float)N_EDGES;
    const float invN = 1.f / (float)N_NODES;

    k_wsum<<<40, 256>>>(emb, conv_w);                                   // 0
    k_wsplit<<<20, 256>>>(Aw, Bw, Cw, Dw, Ew);                          // 1
    k_W2<<<(10 * 16 * DIM + 255) / 256, 256>>>();                       // 2
    k_seq<<<N_NODES / 8, 512, smemS>>>(reads, conv_b);                  // 3
    k_node_gemm<<<(N_NODES + 127) / 128, 512, smemG>>>(                 // 4
        0, Ab, Bb, Db, Eb);
    k_edge_pass1<<<N_EDGES / 128, 512, smemE>>>(                        // 5
        0, Cb, src, dst, sim, length, ee_w, ee_b);

    k_csr_zero<<<(N_NODES + 255) / 256, 256>>>();
    k_hist<<<N_EDGES / 256, 256>>>(dst);
    k_scan<<<1, 1024>>>();
    k_scatter<<<N_EDGES / 256, 256>>>(dst);

    k_bn_final<<<1, 128>>>(bne_g, bne_b, invE);
    k_agg_fused<<<N_NODES, 128>>>(src, sim, length, ee_w, ee_b, 0);
    k_bn_final<<<1, 128>>>(bnh_g, bnh_b, invN);
    k_node_update<<<(N_NODES * 32) / 256, 256>>>();

    for (int i = 1; i < N_LAYERS; i++) {
        const int bo = i * DIM;
        k_node_gemm<<<(N_NODES + 127) / 128, 512, smemG>>>(
            i, Ab + bo, Bb + bo, Db + bo, Eb + bo);
        k_edge_pass1<<<N_EDGES / 128, 512, smemE>>>(
            i, Cb + bo, src, dst, sim, length, ee_w, ee_b);
        k_bn_final<<<1, 128>>>(bne_g + bo, bne_b + bo, invE);
        k_agg_fused<<<N_NODES, 128>>>(src, sim, length, ee_w, ee_b, i);
        k_bn_final<<<1, 128>>>(bnh_g + bo, bnh_b + bo, invN);
        k_node_update<<<(N_NODES * 32) / 256, 256>>>();
    }
    k_dec<<<(N_EDGES * 32 + 255) / 256, 256>>>(dec_w, dec_b, src, dst, out);
}

// round 13
// speedup vs baseline: 1.2573x; 1.0712x over previous
#include <cuda_runtime.h>
#include <cuda_fp16.h>
#include <cstdint>

#define N_NODES 20000
#define READ_LEN 64
#define N_EDGES 320000
#define DIM 128
#define KSZ 20
#define CONV_T (READ_LEN - KSZ + 1)
#define N_LAYERS 4
#define EPS_BN 1e-5f
#define EPS_AGG 1e-6f

#define SBF 136   // half smem row stride (272B): 16B-aligned rows, ldsm conflict-free
#define SCF 132   // fp32 C smem row stride

// ---------------- device scratch ----------------
__device__ float g_h[N_NODES * DIM];
__device__ half  g_e16[(size_t)N_EDGES * DIM];       // fp16 e
__device__ half  g_ehat[(size_t)N_EDGES * DIM];      // fp16 ehat
__device__ float g_Ah[N_NODES * DIM];
__device__ float g_Bh[N_NODES * DIM];
__device__ float g_Dh[N_NODES * DIM];
__device__ float g_Eh[N_NODES * DIM];
__device__ float g_t[N_NODES * DIM];
__device__ float g_wsum[4 * KSZ * DIM];
__device__ float g_W2[10 * 16 * DIM];
__device__ half  g_Whi[20 * 128 * SBF];              // pre-split weights (smem image)
__device__ float g_stats[2 * DIM];                   // zero-init; bn_final restores zeros
__device__ float g_bn_scale[DIM];
__device__ float g_bn_shift[DIM];
__device__ int g_cnt[N_NODES];
__device__ int g_off[N_NODES + 1];
__device__ int g_cur[N_NODES];
__device__ int g_eids[N_EDGES];

// ---------------- mma helpers ----------------
__device__ __forceinline__ unsigned s2u(const void* p)
{
    return (unsigned)__cvta_generic_to_shared(p);
}
__device__ __forceinline__ void ldsm4(unsigned* r, unsigned addr)
{
    asm volatile("ldmatrix.sync.aligned.m8n8.x4.shared.b16 {%0,%1,%2,%3}, [%4];"
                 : "=r"(r[0]), "=r"(r[1]), "=r"(r[2]), "=r"(r[3]) : "r"(addr));
}
__device__ __forceinline__ void mma16816(float* c, const unsigned* a, const unsigned* b)
{
    asm volatile("mma.sync.aligned.m16n8k16.row.col.f32.f16.f16.f32 "
                 "{%0,%1,%2,%3}, {%4,%5,%6,%7}, {%8,%9}, {%0,%1,%2,%3};"
                 : "+f"(c[0]), "+f"(c[1]), "+f"(c[2]), "+f"(c[3])
                 : "r"(a[0]), "r"(a[1]), "r"(a[2]), "r"(a[3]), "r"(b[0]), "r"(b[1]));
}

// pack 4 fp32 into hi/lo fp16 pairs and store to smem tile offset
__device__ __forceinline__ void split_store(half* hi, half* lo, int off4, float4 v)
{
    half hx = __float2half_rn(v.x), hy = __float2half_rn(v.y);
    half hz = __float2half_rn(v.z), hw = __float2half_rn(v.w);
    half2 hp0 = __halves2half2(hx, hy), hp1 = __halves2half2(hz, hw);
    half2 lp0 = __floats2half2_rn(v.x - __half2float(hx), v.y - __half2float(hy));
    half2 lp1 = __floats2half2_rn(v.z - __half2float(hz), v.w - __half2float(hw));
    *(uint2*)(hi + off4) = make_uint2(*(unsigned*)&hp0, *(unsigned*)&hp1);
    *(uint2*)(lo + off4) = make_uint2(*(unsigned*)&lp0, *(unsigned*)&lp1);
}

// split fp32 tile [rows<=128][128] into hi/lo fp16 smem tiles (512 threads)
__device__ __forceinline__ void split_tileA(const float* __restrict__ g, int rows,
                                            half* hi, half* lo, int tid)
{
#pragma unroll
    for (int i = tid; i < 128 * 32; i += 512) {
        int r = i >> 5, c = (i & 31) << 2;
        float4 v = make_float4(0.f, 0.f, 0.f, 0.f);
        if (r < rows) v = *(const float4*)(g + r * 128 + c);
        split_store(hi, lo, r * SBF + c, v);
    }
}

// mainloop (per warp, 32x32 tile): TWO=1: acc += Ahi*W + Alo*W; TWO=0: acc += Ahi*W
template <int TWO>
__device__ __forceinline__ void mma_mainloop(const half* ahi, const half* alo,
                                             const half* whi,
                                             int m0w, int n0w, int lane,
                                             float acc[2][4][4])
{
    int aoff = (lane & 15) * SBF + (lane >> 4) * 8;
    int boff = ((lane & 7) + ((lane >> 4) << 3)) * SBF + ((lane >> 3) & 1) * 8;
#pragma unroll
    for (int kt = 0; kt < 8; kt++) {
        unsigned bf[2][4];
#pragma unroll
        for (int np = 0; np < 2; np++) {
            int o = (n0w + np * 16) * SBF + boff + kt * 16;
            ldsm4(bf[np], s2u(whi + o));
        }
        unsigned af[2][4];
#pragma unroll
        for (int ms = 0; ms < 2; ms++) {
            int o = (m0w + ms * 16) * SBF + aoff + kt * 16;
            ldsm4(af[ms], s2u(ahi + o));
        }
#pragma unroll
        for (int ms = 0; ms < 2; ms++)
#pragma unroll
            for (int nt = 0; nt < 4; nt++)
                mma16816(acc[ms][nt], af[ms], &bf[nt >> 1][(nt & 1) * 2]);
        if (TWO) {
#pragma unroll
            for (int ms = 0; ms < 2; ms++) {
                int o = (m0w + ms * 16) * SBF + aoff + kt * 16;
                ldsm4(af[ms], s2u(alo + o));      // overwrite hi frags
            }
#pragma unroll
            for (int ms = 0; ms < 2; ms++)
#pragma unroll
                for (int nt = 0; nt < 4; nt++)
                    mma16816(acc[ms][nt], af[ms], &bf[nt >> 1][(nt & 1) * 2]);
        }
    }
}

// ---------------- prep ----------------
__global__ void k_wsum(const float* __restrict__ emb, const float* __restrict__ cw)
{
    int idx = blockIdx.x * 256 + threadIdx.x;
    if (idx >= 4 * KSZ * DIM) return;
    int d = idx & 127;
    int bk = idx >> 7;
    int k = bk % KSZ, b = bk / KSZ;
    float s = 0.f;
#pragma unroll
    for (int c = 0; c < 3; c++) s += emb[b * 3 + c] * cw[d * 3 * KSZ + c * KSZ + k];
    g_wsum[idx] = s;
}

__global__ void k_wsplit(const float* __restrict__ Aw, const float* __restrict__ Bw,
                         const float* __restrict__ Cw, const float* __restrict__ Dw,
                         const float* __restrict__ Ew)
{
    int m = blockIdx.x, tid = threadIdx.x;   // 20 blocks
    int lay = m / 5, which = m % 5;
    const float* srcs[5] = {Aw, Bw, Dw, Ew, Cw};
    const float* src = srcs[which] + lay * DIM * DIM;
    half* dst = g_Whi + (size_t)m * 128 * SBF;
    for (int i = tid; i < 128 * 128; i += 256) {
        int r = i >> 7, c = i & 127;
        dst[r * SBF + c] = __float2half_rn(src[i]);
    }
}

__global__ void k_W2()
{
    int idx = blockIdx.x * 256 + threadIdx.x;
    if (idx >= 10 * 16 * DIM) return;
    int d = idx & 127;
    int r = idx >> 7;
    int c2 = r & 15, k2 = r >> 4;
    int a = c2 >> 2, b = c2 & 3;
    g_W2[idx] = g_wsum[(a * KSZ + 2 * k2) * DIM + d] + g_wsum[(b * KSZ + 2 * k2 + 1) * DIM + d];
}

__global__ __launch_bounds__(512) void k_seq(const int* __restrict__ reads,
                                             const float* __restrict__ conv_b)
{
    extern __shared__ float sm[];
    float* sW2 = sm;
    int* scode = (int*)(sm + 10 * 16 * DIM);
    int* spc = scode + 512;
    int tid = threadIdx.x;

    for (int i = tid; i < (10 * 16 * DIM) / 4; i += 512)
        ((float4*)sW2)[i] = ((const float4*)g_W2)[i];

    int nl = tid >> 6, l = tid & 63;
    int n = blockIdx.x * 8 + nl;
    scode[tid] = reads[n * READ_LEN + l];
    __syncthreads();
    if (l < 63) spc[tid] = (scode[tid] * 4 + scode[tid + 1]) << 7;
    __syncthreads();

    int dp = tid & 63;
    const float* wd = sW2 + dp * 2;
    const int* pc = spc + nl * 64;
    float m0 = -3.4e38f, m1 = -3.4e38f;
#pragma unroll
    for (int t = 0; t < CONV_T; t++) {
        float s0 = 0.f, s1 = 0.f;
#pragma unroll
        for (int k2 = 0; k2 < 10; k2++) {
            float2 v = *(const float2*)(wd + pc[t + 2 * k2] + k2 * 2048);
            s0 += v.x; s1 += v.y;
        }
        m0 = fmaxf(m0, s0);
        m1 = fmaxf(m1, s1);
    }
    float2 bv = *(const float2*)(conv_b + dp * 2);
    float2 hv;
    hv.x = fmaxf(m0 + bv.x, 0.f);
    hv.y = fmaxf(m1 + bv.y, 0.f);
    *(float2*)(g_h + n * DIM + dp * 2) = hv;
}

// ---------------- CSR build by dst ----------------
__global__ void k_csr_zero()
{
    int i = blockIdx.x * 256 + threadIdx.x;
    if (i < N_NODES) g_cnt[i] = 0;
}
__global__ void k_hist(const int* __restrict__ dst)
{
    int i = blockIdx.x * 256 + threadIdx.x;
    if (i < N_EDGES) atomicAdd(&g_cnt[dst[i]], 1);
}
__global__ __launch_bounds__(1024) void k_scan()
{
    __shared__ int sd[1024];
    int tid = threadIdx.x;
    int carry = 0;
    for (int base = 0; base < N_NODES; base += 1024) {
        int i = base + tid;
        int v = (i < N_NODES) ? g_cnt[i] : 0;
        __syncthreads();
        sd[tid] = v;
        __syncthreads();
        for (int ofs = 1; ofs < 1024; ofs <<= 1) {
            int t = (tid >= ofs) ? sd[tid - ofs] : 0;
            __syncthreads();
            sd[tid] += t;
            __syncthreads();
        }
        if (i < N_NODES) {
            int ex = carry + sd[tid] - v;
            g_off[i] = ex;
            g_cur[i] = ex;
        }
        carry += sd[1023];
    }
    if (tid == 0) g_off[N_NODES] = carry;
}
__global__ void k_scatter(const int* __restrict__ dst)
{
    int i = blockIdx.x * 256 + threadIdx.x;
    if (i < N_EDGES) {
        int p = atomicAdd(&g_cur[dst[i]], 1);
        g_eids[p] = i;
    }
}

// ---------------- BN finalize (restores g_stats zero invariant) ----------------
__global__ __launch_bounds__(128) void k_bn_final(const float* __restrict__ g,
                                                  const float* __restrict__ b,
                                                  float invc)
{
    int d = threadIdx.x;
    float s = g_stats[d], sq = g_stats[128 + d];
    float mean = s * invc;
    float var = sq * invc - mean * mean;
    float sc = g[d] * rsqrtf(var + EPS_BN);
    g_bn_scale[d] = sc;
    g_bn_shift[d] = b[d] - mean * sc;
    g_stats[d] = 0.f;
    g_stats[128 + d] = 0.f;
}

// ---------------- node GEMM: Ah,Bh,Dh,Eh = h @ W.T + b ----------------
__global__ __launch_bounds__(512, 2) void k_node_gemm(
    int lay,
    const float* __restrict__ Ba, const float* __restrict__ Bb_,
    const float* __restrict__ Bd, const float* __restrict__ Be)
{
    const float* Bp[4] = {Ba, Bb_, Bd, Be};
    float* Op[4] = {g_Ah, g_Bh, g_Dh, g_Eh};
    extern __shared__ char smc[];
    half* ahi = (half*)smc;
    half* alo = ahi + 128 * SBF;
    half* whi = alo + 128 * SBF;

    int tid = threadIdx.x;
    int lane = tid & 31, w = tid >> 5;
    int m0w = (w & 3) * 32, n0w = (w >> 2) * 32;
    int n0 = blockIdx.x * 128;
    int mlim = N_NODES - n0;
    if (mlim > 128) mlim = 128;

    split_tileA(g_h + (size_t)n0 * 128, mlim, ahi, alo, tid);

    for (int mat = 0; mat < 4; mat++) {
        __syncthreads();
        const uint2* wsrc = (const uint2*)(g_Whi + (size_t)(lay * 5 + mat) * 128 * SBF);
        for (int i = tid; i < (128 * SBF) / 4; i += 512) ((uint2*)whi)[i] = wsrc[i];
        __syncthreads();
        float acc[2][4][4];
#pragma unroll
        for (int ms = 0; ms < 2; ms++)
#pragma unroll
            for (int nt = 0; nt < 4; nt++)
#pragma unroll
                for (int j = 0; j < 4; j++) acc[ms][nt][j] = 0.f;

        mma_mainloop<1>(ahi, alo, whi, m0w, n0w, lane, acc);

        float* Out = Op[mat];
        const float* Bias = Bp[mat];
#pragma unroll
        for (int ms = 0; ms < 2; ms++)
#pragma unroll
            for (int nt = 0; nt < 4; nt++) {
                int col = n0w + nt * 8 + (lane & 3) * 2;
                float2 bv = *(const float2*)(Bias + col);
                int r0 = m0w + ms * 16 + (lane >> 2);
                if (r0 < mlim) {
                    float2 v = {acc[ms][nt][0] + bv.x, acc[ms][nt][1] + bv.y};
                    *(float2*)(Out + (size_t)(n0 + r0) * 128 + col) = v;
                }
                if (r0 + 8 < mlim) {
                    float2 v = {acc[ms][nt][2] + bv.x, acc[ms][nt][3] + bv.y};
                    *(float2*)(Out + (size_t)(n0 + r0 + 8) * 128 + col) = v;
                }
            }
    }
}

// ---------------- edge pass1: ehat = e@Cw.T + Cb + Dh[dst] + Eh[src]; BN stats --------
// LAY0: e tile computed from sim/len/ee_w/ee_b (two-term split)
// else: e tile copied from fp16 g_e16 (single-term: lo == 0 exactly)
template <bool LAY0>
__global__ __launch_bounds__(512, 2) void k_edge_pass1(int lay,
                                                       const float* __restrict__ Cb,
                                                       const int* __restrict__ src,
                                                       const int* __restrict__ dst,
                                                       const float* __restrict__ sim,
                                                       const float* __restrict__ len,
                                                       const float* __restrict__ ew,
                                                       const float* __restrict__ eb)
{
    extern __shared__ char smc[];
    half* ahi = (half*)smc;
    half* alo = ahi + 128 * SBF;
    half* whi = alo + 128 * SBF;
    float* Csm = (float*)smc;                     // aliases ahi/alo after mma
    char* tail = smc + 3 * 128 * SBF * 2;
    int* s_src = (int*)tail;
    int* s_dst = s_src + 128;
    float* ssum = (float*)(s_dst + 128);
    float* ssq = ssum + 128;
    float* ssim = ssq + 128;
    float* slen = ssim + 128;
    float* sw0 = slen + 128;
    float* sw1 = sw0 + 128;
    float* sb = sw1 + 128;

    int tid = threadIdx.x;
    int lane = tid & 31, w = tid >> 5;
    int m0w = (w & 3) * 32, n0w = (w >> 2) * 32;
    int e0 = blockIdx.x * 128;

    if (tid < 128) {
        s_src[tid] = src[e0 + tid];
        s_dst[tid] = dst[e0 + tid];
        ssum[tid] = 0.f;
        ssq[tid] = 0.f;
    }
    if (LAY0) {
        if (tid < 128) {
            ssim[tid] = sim[e0 + tid];
            slen[tid] = len[e0 + tid];
            sw0[tid] = ew[tid * 2];
            sw1[tid] = ew[tid * 2 + 1];
            sb[tid] = eb[tid];
        }
        __syncthreads();
#pragma unroll
        for (int i = tid; i < 128 * 32; i += 512) {
            int r = i >> 5, c = (i & 31) << 2;
            float s_ = ssim[r], l_ = slen[r];
            float4 v;
            v.x = fmaf(s_, sw0[c + 0], fmaf(l_, sw1[c + 0], sb[c + 0]));
            v.y = fmaf(s_, sw0[c + 1], fmaf(l_, sw1[c + 1], sb[c + 1]));
            v.z = fmaf(s_, sw0[c + 2], fmaf(l_, sw1[c + 2], sb[c + 2]));
            v.w = fmaf(s_, sw0[c + 3], fmaf(l_, sw1[c + 3], sb[c + 3]));
            split_store(ahi, alo, r * SBF + c, v);
        }
    } else {
        // e is fp16: copy rows straight into ahi (lo tile unused)
#pragma unroll
        for (int i = tid; i < 128 * 32; i += 512) {
            int r = i >> 5, c = (i & 31) << 2;
            *(uint2*)(ahi + r * SBF + c) =
                *(const uint2*)(g_e16 + (size_t)(e0 + r) * 128 + c);
        }
    }
    {
        const uint2* wsrc = (const uint2*)(g_Whi + (size_t)(lay * 5 + 4) * 128 * SBF);
        for (int i = tid; i < (128 * SBF) / 4; i += 512) ((uint2*)whi)[i] = wsrc[i];
    }
    __syncthreads();

    float acc[2][4][4];
#pragma unroll
    for (int ms = 0; ms < 2; ms++)
#pragma unroll
        for (int nt = 0; nt < 4; nt++)
#pragma unroll
            for (int j = 0; j < 4; j++) acc[ms][nt][j] = 0.f;

    if (LAY0)
        mma_mainloop<1>(ahi, alo, whi, m0w, n0w, lane, acc);
    else
        mma_mainloop<0>(ahi, alo, whi, m0w, n0w, lane, acc);

    __syncthreads();      // A tiles dead; Csm aliases them
#pragma unroll
    for (int ms = 0; ms < 2; ms++)
#pragma unroll
        for (int nt = 0; nt < 4; nt++) {
            int col = n0w + nt * 8 + (lane & 3) * 2;
            int r0 = m0w + ms * 16 + (lane >> 2);
            *(float2*)(Csm + r0 * SCF + col) = make_float2(acc[ms][nt][0], acc[ms][nt][1]);
            *(float2*)(Csm + (r0 + 8) * SCF + col) = make_float2(acc[ms][nt][2], acc[ms][nt][3]);
        }
    __syncthreads();

    // add Cb + Dh[dst] + Eh[src] in Csm (16 warps x 8 rows), accumulate stats
    int colg = (tid & 31) << 2;
    int r0 = (tid >> 5) << 3;
    float4 cb4 = *(const float4*)(Cb + colg);
    float s0 = 0.f, s1 = 0.f, s2 = 0.f, s3 = 0.f;
    float q0 = 0.f, q1 = 0.f, q2 = 0.f, q3 = 0.f;
#pragma unroll
    for (int j = 0; j < 8; j++) {
        int r = r0 + j;
        float* crow = Csm + r * SCF + colg;
        float4 c = *(const float4*)crow;
        int dd = s_dst[r], sr = s_src[r];
        float4 dh = *(const float4*)(g_Dh + (size_t)dd * 128 + colg);
        float4 eh = *(const float4*)(g_Eh + (size_t)sr * 128 + colg);
        float4 v;
        v.x = c.x + cb4.x + dh.x + eh.x;
        v.y = c.y + cb4.y + dh.y + eh.y;
        v.z = c.z + cb4.z + dh.z + eh.z;
        v.w = c.w + cb4.w + dh.w + eh.w;
        *(float4*)crow = v;
        s0 += v.x; q0 += v.x * v.x;
        s1 += v.y; q1 += v.y * v.y;
        s2 += v.z; q2 += v.z * v.z;
        s3 += v.w; q3 += v.w * v.w;
    }
    atomicAdd(&ssum[colg + 0], s0); atomicAdd(&ssq[colg + 0], q0);
    atomicAdd(&ssum[colg + 1], s1); atomicAdd(&ssq[colg + 1], q1);
    atomicAdd(&ssum[colg + 2], s2); atomicAdd(&ssq[colg + 2], q2);
    atomicAdd(&ssum[colg + 3], s3); atomicAdd(&ssq[colg + 3], q3);
    __syncthreads();

    // coalesced fp16 ehat store
    for (int i = tid; i < 128 * 32; i += 512) {
        int r = i >> 5, c4 = (i & 31) << 2;
        float4 v = *(const float4*)(Csm + r * SCF + c4);
        half2 p0 = __floats2half2_rn(v.x, v.y);
        half2 p1 = __floats2half2_rn(v.z, v.w);
        *(uint2*)(g_ehat + (size_t)(e0 + r) * 128 + c4) =
            make_uint2(*(unsigned*)&p0, *(unsigned*)&p1);
    }
    if (tid < 128) {
        atomicAdd(&g_stats[tid], ssum[tid]);
        atomicAdd(&g_stats[128 + tid], ssq[tid]);
    }
}

// ---------------- fused agg (1 node/block): e update + aggregation + t + stats ----------
__global__ __launch_bounds__(128) void k_agg_fused(const int* __restrict__ src,
                                                   const float* __restrict__ sim,
                                                   const float* __restrict__ len,
                                                   const float* __restrict__ ew,
                                                   const float* __restrict__ eb,
                                                   int lay)
{
    int n = blockIdx.x;
    int d = threadIdx.x;
    int beg = g_off[n], end = g_off[n + 1];
    float sc = g_bn_scale[d], sh = g_bn_shift[d];
    float w0 = 0.f, w1 = 0.f, b0 = 0.f;
    if (lay == 0) {
        w0 = ew[d * 2];
        w1 = ew[d * 2 + 1];
        b0 = eb[d];
    }
    float num = 0.f, den = 0.f;
    for (int j = beg; j < end; j++) {
        int eid = g_eids[j];
        float x = __half2float(g_ehat[(size_t)eid * 128 + d]);
        float s = 1.f / (1.f + __expf(-x));
        num += s * g_Bh[(size_t)src[eid] * 128 + d];
        den += s;
        float rel = fmaxf(fmaf(x, sc, sh), 0.f);
        half* ep = g_e16 + (size_t)eid * 128 + d;
        if (lay == 0) {
            float e0v = fmaf(sim[eid], w0, fmaf(len[eid], w1, b0));
            *ep = __float2half_rn(e0v + rel);
        } else {
            *ep = __float2half_rn(__half2float(*ep) + rel);
        }
    }
    float t = g_Ah[n * 128 + d] + num / (den + EPS_AGG);
    g_t[n * 128 + d] = t;
    atomicAdd(&g_stats[d], t);
    atomicAdd(&g_stats[128 + d], t * t);
}

// ---------------- h += relu(bn(t)) ----------------
__global__ __launch_bounds__(256) void k_node_update()
{
    int i = blockIdx.x * 256 + threadIdx.x;
    int d4 = (i & 31) << 2;
    float4 sc = *(const float4*)(g_bn_scale + d4);
    float4 sh = *(const float4*)(g_bn_shift + d4);
    float4 x = ((const float4*)g_t)[i];
    float4 hv = ((const float4*)g_h)[i];
    hv.x += fmaxf(fmaf(x.x, sc.x, sh.x), 0.f);
    hv.y += fmaxf(fmaf(x.y, sc.y, sh.y), 0.f);
    hv.z += fmaxf(fmaf(x.z, sc.z, sh.z), 0.f);
    hv.w += fmaxf(fmaf(x.w, sc.w, sh.w), 0.f);
    ((float4*)g_h)[i] = hv;
}

// ---------------- decoder ----------------
__global__ __launch_bounds__(256) void k_dec(const float* __restrict__ dw,
                                             const float* __restrict__ db,
                                             const int* __restrict__ src,
                                             const int* __restrict__ dst,
                                             float* __restrict__ out)
{
    int w = (blockIdx.x * 256 + threadIdx.x) >> 5;
    if (w >= N_EDGES) return;
    int lane = threadIdx.x & 31;
    int s = src[w], d = dst[w];
    float4 w1 = *(const float4*)(dw + lane * 4);
    float4 w2 = *(const float4*)(dw + 128 + lane * 4);
    float4 w3 = *(const float4*)(dw + 256 + lane * 4);
    float4 hs = *(const float4*)(g_h + (size_t)s * 128 + lane * 4);
    float4 hd = *(const float4*)(g_h + (size_t)d * 128 + lane * 4);
    uint2 ep = *(const uint2*)(g_e16 + (size_t)w * 128 + lane * 4);
    half2 e01 = *(half2*)&ep.x, e23 = *(half2*)&ep.y;
    float2 ef0 = __half22float2(e01), ef1 = __half22float2(e23);
    float acc = w1.x * hs.x + w1.y * hs.y + w1.z * hs.z + w1.w * hs.w
              + w2.x * hd.x + w2.y * hd.y + w2.z * hd.z + w2.w * hd.w
              + w3.x * ef0.x + w3.y * ef0.y + w3.z * ef1.x + w3.w * ef1.y;
#pragma unroll
    for (int ofs = 16; ofs > 0; ofs >>= 1) acc += __shfl_down_sync(0xffffffffu, acc, ofs);
    if (lane == 0) out[w] = acc + db[0];
}

// ---------------- launcher ----------------
extern "C" void kernel_launch(void* const* d_in, const int* in_sizes, int n_in,
                              void* d_out, int out_size)
{
    const float* emb    = (const float*)d_in[0];
    const float* conv_w = (const float*)d_in[1];
    const float* conv_b = (const float*)d_in[2];
    const float* ee_w   = (const float*)d_in[3];
    const float* ee_b   = (const float*)d_in[4];
    const float* Aw     = (const float*)d_in[5];
    const float* Ab     = (const float*)d_in[6];
    const float* Bw     = (const float*)d_in[7];
    const float* Bb     = (const float*)d_in[8];
    const float* Cw     = (const float*)d_in[9];
    const float* Cb     = (const float*)d_in[10];
    const float* Dw     = (const float*)d_in[11];
    const float* Db     = (const float*)d_in[12];
    const float* Ew     = (const float*)d_in[13];
    const float* Eb     = (const float*)d_in[14];
    const float* bnh_g  = (const float*)d_in[15];
    const float* bnh_b  = (const float*)d_in[16];
    const float* bne_g  = (const float*)d_in[17];
    const float* bne_b  = (const float*)d_in[18];
    const float* dec_w  = (const float*)d_in[19];
    const float* dec_b  = (const float*)d_in[20];
    const float* sim    = (const float*)d_in[21];
    const float* length = (const float*)d_in[22];
    const int*   reads  = (const int*)d_in[23];
    const int*   src    = (const int*)d_in[24];
    const int*   dst    = (const int*)d_in[25];
    float* out = (float*)d_out;

    const int smemG = 3 * 128 * SBF * 2;                  // 104448 -> 2 blocks/SM
    const int smemE = smemG + 9 * 128 * 4;                 // 109056 -> 2 blocks/SM
    const int smemS = (10 * 16 * DIM) * 4 + 2 * 512 * 4;   // 86016
    cudaFuncSetAttribute(k_node_gemm, cudaFuncAttributeMaxDynamicSharedMemorySize, smemG);
    cudaFuncSetAttribute(k_edge_pass1<true>, cudaFuncAttributeMaxDynamicSharedMemorySize, smemE);
    cudaFuncSetAttribute(k_edge_pass1<false>, cudaFuncAttributeMaxDynamicSharedMemorySize, smemE);
    cudaFuncSetAttribute(k_seq, cudaFuncAttributeMaxDynamicSharedMemorySize, smemS);

    const float invE = 1.f / (float)N_EDGES;
    const float invN = 1.f / (float)N_NODES;

    k_wsum<<<40, 256>>>(emb, conv_w);                                   // 0
    k_wsplit<<<20, 256>>>(Aw, Bw, Cw, Dw, Ew);                          // 1
    k_W2<<<(10 * 16 * DIM + 255) / 256, 256>>>();                       // 2
    k_seq<<<N_NODES / 8, 512, smemS>>>(reads, conv_b);                  // 3
    k_node_gemm<<<(N_NODES + 127) / 128, 512, smemG>>>(                 // 4
        0, Ab, Bb, Db, Eb);
    k_edge_pass1<true><<<N_EDGES / 128, 512, smemE>>>(                  // 5
        0, Cb, src, dst, sim, length, ee_w, ee_b);

    k_csr_zero<<<(N_NODES + 255) / 256, 256>>>();
    k_hist<<<N_EDGES / 256, 256>>>(dst);
    k_scan<<<1, 1024>>>();
    k_scatter<<<N_EDGES / 256, 256>>>(dst);

    k_bn_final<<<1, 128>>>(bne_g, bne_b, invE);
    k_agg_fused<<<N_NODES, 128>>>(src, sim, length, ee_w, ee_b, 0);
    k_bn_final<<<1, 128>>>(bnh_g, bnh_b, invN);
    k_node_update<<<(N_NODES * 32) / 256, 256>>>();

    for (int i = 1; i < N_LAYERS; i++) {
        const int bo = i * DIM;
        k_node_gemm<<<(N_NODES + 127) / 128, 512, smemG>>>(
            i, Ab + bo, Bb + bo, Db + bo, Eb + bo);
        k_edge_pass1<false><<<N_EDGES / 128, 512, smemE>>>(
            i, Cb + bo, src, dst, sim, length, ee_w, ee_b);
        k_bn_final<<<1, 128>>>(bne_g + bo, bne_b + bo, invE);
        k_agg_fused<<<N_NODES, 128>>>(src, sim, length, ee_w, ee_b, i);
        k_bn_final<<<1, 128>>>(bnh_g + bo, bnh_b + bo, invN);
        k_node_update<<<(N_NODES * 32) / 256, 256>>>();
    }
    k_dec<<<(N_EDGES * 32 + 255) / 256, 256>>>(dec_w, dec_b, src, dst, out);
}

// round 15
// speedup vs baseline: 1.2655x; 1.0065x over previous
#include <cuda_runtime.h>
#include <cuda_fp16.h>
#include <cstdint>

#define N_NODES 20000
#define READ_LEN 64
#define N_EDGES 320000
#define DIM 128
#define KSZ 20
#define CONV_T (READ_LEN - KSZ + 1)
#define N_LAYERS 4
#define EPS_BN 1e-5f
#define EPS_AGG 1e-6f

#define SBF 136   // half smem row stride (272B): 16B-aligned rows, ldsm conflict-free
#define SCF 132   // fp32 C smem row stride

// ---------------- device scratch ----------------
__device__ float g_h[N_NODES * DIM];
__device__ half  g_e16[(size_t)N_EDGES * DIM];       // fp16 e
__device__ half  g_ehat[(size_t)N_EDGES * DIM];      // fp16 ehat
__device__ float g_Ah[N_NODES * DIM];
__device__ float g_Bh[N_NODES * DIM];
__device__ float g_Dh[N_NODES * DIM];
__device__ float g_Eh[N_NODES * DIM];
__device__ float g_t[N_NODES * DIM];
__device__ float g_wsum[4 * KSZ * DIM];
__device__ float g_W2[10 * 16 * DIM];
__device__ half  g_Whi[20 * 128 * SBF];              // pre-split weights (smem image)
__device__ float g_stats_e[2 * DIM];                 // edge BN stats (zero between uses)
__device__ float g_stats_n[2 * DIM];                 // node BN stats (zero between uses)
__device__ int g_cnt[N_NODES];
__device__ int g_off[N_NODES + 1];
__device__ int g_cur[N_NODES];
__device__ int g_eids[N_EDGES];

// ---------------- mma helpers ----------------
__device__ __forceinline__ unsigned s2u(const void* p)
{
    return (unsigned)__cvta_generic_to_shared(p);
}
__device__ __forceinline__ void ldsm4(unsigned* r, unsigned addr)
{
    asm volatile("ldmatrix.sync.aligned.m8n8.x4.shared.b16 {%0,%1,%2,%3}, [%4];"
                 : "=r"(r[0]), "=r"(r[1]), "=r"(r[2]), "=r"(r[3]) : "r"(addr));
}
__device__ __forceinline__ void mma16816(float* c, const unsigned* a, const unsigned* b)
{
    asm volatile("mma.sync.aligned.m16n8k16.row.col.f32.f16.f16.f32 "
                 "{%0,%1,%2,%3}, {%4,%5,%6,%7}, {%8,%9}, {%0,%1,%2,%3};"
                 : "+f"(c[0]), "+f"(c[1]), "+f"(c[2]), "+f"(c[3])
                 : "r"(a[0]), "r"(a[1]), "r"(a[2]), "r"(a[3]), "r"(b[0]), "r"(b[1]));
}

// pack 4 fp32 into hi/lo fp16 pairs and store to smem tile offset
__device__ __forceinline__ void split_store(half* hi, half* lo, int off4, float4 v)
{
    half hx = __float2half_rn(v.x), hy = __float2half_rn(v.y);
    half hz = __float2half_rn(v.z), hw = __float2half_rn(v.w);
    half2 hp0 = __halves2half2(hx, hy), hp1 = __halves2half2(hz, hw);
    half2 lp0 = __floats2half2_rn(v.x - __half2float(hx), v.y - __half2float(hy));
    half2 lp1 = __floats2half2_rn(v.z - __half2float(hz), v.w - __half2float(hw));
    *(uint2*)(hi + off4) = make_uint2(*(unsigned*)&hp0, *(unsigned*)&hp1);
    *(uint2*)(lo + off4) = make_uint2(*(unsigned*)&lp0, *(unsigned*)&lp1);
}

// split fp32 tile [rows<=128][128] into hi/lo fp16 smem tiles (512 threads)
__device__ __forceinline__ void split_tileA(const float* __restrict__ g, int rows,
                                            half* hi, half* lo, int tid)
{
#pragma unroll
    for (int i = tid; i < 128 * 32; i += 512) {
        int r = i >> 5, c = (i & 31) << 2;
        float4 v = make_float4(0.f, 0.f, 0.f, 0.f);
        if (r < rows) v = *(const float4*)(g + r * 128 + c);
        split_store(hi, lo, r * SBF + c, v);
    }
}

// mainloop (per warp, 32x32 tile): TWO=1: acc += Ahi*W + Alo*W; TWO=0: acc += Ahi*W
template <int TWO>
__device__ __forceinline__ void mma_mainloop(const half* ahi, const half* alo,
                                             const half* whi,
                                             int m0w, int n0w, int lane,
                                             float acc[2][4][4])
{
    int aoff = (lane & 15) * SBF + (lane >> 4) * 8;
    int boff = ((lane & 7) + ((lane >> 4) << 3)) * SBF + ((lane >> 3) & 1) * 8;
#pragma unroll
    for (int kt = 0; kt < 8; kt++) {
        unsigned bf[2][4];
#pragma unroll
        for (int np = 0; np < 2; np++) {
            int o = (n0w + np * 16) * SBF + boff + kt * 16;
            ldsm4(bf[np], s2u(whi + o));
        }
        unsigned af[2][4];
#pragma unroll
        for (int ms = 0; ms < 2; ms++) {
            int o = (m0w + ms * 16) * SBF + aoff + kt * 16;
            ldsm4(af[ms], s2u(ahi + o));
        }
#pragma unroll
        for (int ms = 0; ms < 2; ms++)
#pragma unroll
            for (int nt = 0; nt < 4; nt++)
                mma16816(acc[ms][nt], af[ms], &bf[nt >> 1][(nt & 1) * 2]);
        if (TWO) {
#pragma unroll
            for (int ms = 0; ms < 2; ms++) {
                int o = (m0w + ms * 16) * SBF + aoff + kt * 16;
                ldsm4(af[ms], s2u(alo + o));      // overwrite hi frags
            }
#pragma unroll
            for (int ms = 0; ms < 2; ms++)
#pragma unroll
                for (int nt = 0; nt < 4; nt++)
                    mma16816(acc[ms][nt], af[ms], &bf[nt >> 1][(nt & 1) * 2]);
        }
    }
}

// ---------------- prep ----------------
__global__ void k_wsum(const float* __restrict__ emb, const float* __restrict__ cw)
{
    int idx = blockIdx.x * 256 + threadIdx.x;
    if (idx >= 4 * KSZ * DIM) return;
    int d = idx & 127;
    int bk = idx >> 7;
    int k = bk % KSZ, b = bk / KSZ;
    float s = 0.f;
#pragma unroll
    for (int c = 0; c < 3; c++) s += emb[b * 3 + c] * cw[d * 3 * KSZ + c * KSZ + k];
    g_wsum[idx] = s;
}

__global__ void k_wsplit(const float* __restrict__ Aw, const float* __restrict__ Bw,
                         const float* __restrict__ Cw, const float* __restrict__ Dw,
                         const float* __restrict__ Ew)
{
    int m = blockIdx.x, tid = threadIdx.x;   // 20 blocks
    int lay = m / 5, which = m % 5;
    const float* srcs[5] = {Aw, Bw, Dw, Ew, Cw};
    const float* src = srcs[which] + lay * DIM * DIM;
    half* dst = g_Whi + (size_t)m * 128 * SBF;
    for (int i = tid; i < 128 * 128; i += 256) {
        int r = i >> 7, c = i & 127;
        dst[r * SBF + c] = __float2half_rn(src[i]);
    }
}

__global__ void k_W2()
{
    int idx = blockIdx.x * 256 + threadIdx.x;
    if (idx >= 10 * 16 * DIM) return;
    int d = idx & 127;
    int r = idx >> 7;
    int c2 = r & 15, k2 = r >> 4;
    int a = c2 >> 2, b = c2 & 3;
    g_W2[idx] = g_wsum[(a * KSZ + 2 * k2) * DIM + d] + g_wsum[(b * KSZ + 2 * k2 + 1) * DIM + d];
}

__global__ __launch_bounds__(512) void k_seq(const int* __restrict__ reads,
                                             const float* __restrict__ conv_b)
{
    extern __shared__ float sm[];
    float* sW2 = sm;
    int* scode = (int*)(sm + 10 * 16 * DIM);
    int* spc = scode + 512;
    int tid = threadIdx.x;

    for (int i = tid; i < (10 * 16 * DIM) / 4; i += 512)
        ((float4*)sW2)[i] = ((const float4*)g_W2)[i];

    int nl = tid >> 6, l = tid & 63;
    int n = blockIdx.x * 8 + nl;
    scode[tid] = reads[n * READ_LEN + l];
    __syncthreads();
    if (l < 63) spc[tid] = (scode[tid] * 4 + scode[tid + 1]) << 7;
    __syncthreads();

    int dp = tid & 63;
    const float* wd = sW2 + dp * 2;
    const int* pc = spc + nl * 64;
    float m0 = -3.4e38f, m1 = -3.4e38f;
#pragma unroll
    for (int t = 0; t < CONV_T; t++) {
        float s0 = 0.f, s1 = 0.f;
#pragma unroll
        for (int k2 = 0; k2 < 10; k2++) {
            float2 v = *(const float2*)(wd + pc[t + 2 * k2] + k2 * 2048);
            s0 += v.x; s1 += v.y;
        }
        m0 = fmaxf(m0, s0);
        m1 = fmaxf(m1, s1);
    }
    float2 bv = *(const float2*)(conv_b + dp * 2);
    float2 hv;
    hv.x = fmaxf(m0 + bv.x, 0.f);
    hv.y = fmaxf(m1 + bv.y, 0.f);
    *(float2*)(g_h + n * DIM + dp * 2) = hv;
}

// ---------------- CSR build by dst ----------------
__global__ void k_csr_zero()
{
    int i = blockIdx.x * 256 + threadIdx.x;
    if (i < N_NODES) g_cnt[i] = 0;
}
__global__ void k_hist(const int* __restrict__ dst)
{
    int i = blockIdx.x * 256 + threadIdx.x;
    if (i < N_EDGES) atomicAdd(&g_cnt[dst[i]], 1);
}
__global__ __launch_bounds__(1024) void k_scan()
{
    __shared__ int sd[1024];
    int tid = threadIdx.x;
    int carry = 0;
    for (int base = 0; base < N_NODES; base += 1024) {
        int i = base + tid;
        int v = (i < N_NODES) ? g_cnt[i] : 0;
        __syncthreads();
        sd[tid] = v;
        __syncthreads();
        for (int ofs = 1; ofs < 1024; ofs <<= 1) {
            int t = (tid >= ofs) ? sd[tid - ofs] : 0;
            __syncthreads();
            sd[tid] += t;
            __syncthreads();
        }
        if (i < N_NODES) {
            int ex = carry + sd[tid] - v;
            g_off[i] = ex;
            g_cur[i] = ex;
        }
        carry += sd[1023];
    }
    if (tid == 0) g_off[N_NODES] = carry;
}
__global__ void k_scatter(const int* __restrict__ dst)
{
    int i = blockIdx.x * 256 + threadIdx.x;
    if (i < N_EDGES) {
        int p = atomicAdd(&g_cur[dst[i]], 1);
        g_eids[p] = i;
    }
}

// ---------------- node GEMM: Ah,Bh,Dh,Eh = h @ W.T + b ----------------
__global__ __launch_bounds__(512, 2) void k_node_gemm(
    int lay,
    const float* __restrict__ Ba, const float* __restrict__ Bb_,
    const float* __restrict__ Bd, const float* __restrict__ Be)
{
    const float* Bp[4] = {Ba, Bb_, Bd, Be};
    float* Op[4] = {g_Ah, g_Bh, g_Dh, g_Eh};
    extern __shared__ char smc[];
    half* ahi = (half*)smc;
    half* alo = ahi + 128 * SBF;
    half* whi = alo + 128 * SBF;

    int tid = threadIdx.x;
    int lane = tid & 31, w = tid >> 5;
    int m0w = (w & 3) * 32, n0w = (w >> 2) * 32;
    int n0 = blockIdx.x * 128;
    int mlim = N_NODES - n0;
    if (mlim > 128) mlim = 128;

    split_tileA(g_h + (size_t)n0 * 128, mlim, ahi, alo, tid);

    for (int mat = 0; mat < 4; mat++) {
        __syncthreads();
        const uint2* wsrc = (const uint2*)(g_Whi + (size_t)(lay * 5 + mat) * 128 * SBF);
        for (int i = tid; i < (128 * SBF) / 4; i += 512) ((uint2*)whi)[i] = wsrc[i];
        __syncthreads();
        float acc[2][4][4];
#pragma unroll
        for (int ms = 0; ms < 2; ms++)
#pragma unroll
            for (int nt = 0; nt < 4; nt++)
#pragma unroll
                for (int j = 0; j < 4; j++) acc[ms][nt][j] = 0.f;

        mma_mainloop<1>(ahi, alo, whi, m0w, n0w, lane, acc);

        float* Out = Op[mat];
        const float* Bias = Bp[mat];
#pragma unroll
        for (int ms = 0; ms < 2; ms++)
#pragma unroll
            for (int nt = 0; nt < 4; nt++) {
                int col = n0w + nt * 8 + (lane & 3) * 2;
                float2 bv = *(const float2*)(Bias + col);
                int r0 = m0w + ms * 16 + (lane >> 2);
                if (r0 < mlim) {
                    float2 v = {acc[ms][nt][0] + bv.x, acc[ms][nt][1] + bv.y};
                    *(float2*)(Out + (size_t)(n0 + r0) * 128 + col) = v;
                }
                if (r0 + 8 < mlim) {
                    float2 v = {acc[ms][nt][2] + bv.x, acc[ms][nt][3] + bv.y};
                    *(float2*)(Out + (size_t)(n0 + r0 + 8) * 128 + col) = v;
                }
            }
    }
}

// ---------------- edge pass1: ehat = e@Cw.T + Cb + Dh[dst] + Eh[src]; edge BN stats ----
// LAY0: e tile computed from sim/len/ee_w/ee_b (two-term split)
// else: e tile copied from fp16 g_e16 (single-term). Block 0 zeroes g_stats_n.
template <bool LAY0>
__global__ __launch_bounds__(512, 2) void k_edge_pass1(int lay,
                                                       const float* __restrict__ Cb,
                                                       const int* __restrict__ src,
                                                       const int* __restrict__ dst,
                                                       const float* __restrict__ sim,
                                                       const float* __restrict__ len,
                                                       const float* __restrict__ ew,
                                                       const float* __restrict__ eb)
{
    extern __shared__ char smc[];
    half* ahi = (half*)smc;
    half* alo = ahi + 128 * SBF;
    half* whi = alo + 128 * SBF;
    float* Csm = (float*)smc;                     // aliases ahi/alo after mma
    char* tail = smc + 3 * 128 * SBF * 2;
    int* s_src = (int*)tail;
    int* s_dst = s_src + 128;
    float* ssum = (float*)(s_dst + 128);
    float* ssq = ssum + 128;
    float* ssim = ssq + 128;
    float* slen = ssim + 128;
    float* sw0 = slen + 128;
    float* sw1 = sw0 + 128;
    float* sb = sw1 + 128;

    int tid = threadIdx.x;
    int lane = tid & 31, w = tid >> 5;
    int m0w = (w & 3) * 32, n0w = (w >> 2) * 32;
    int e0 = blockIdx.x * 128;

    if (blockIdx.x == 0 && tid < 256) g_stats_n[tid] = 0.f;   // zero node stats for this layer

    if (tid < 128) {
        s_src[tid] = src[e0 + tid];
        s_dst[tid] = dst[e0 + tid];
        ssum[tid] = 0.f;
        ssq[tid] = 0.f;
    }
    if (LAY0) {
        if (tid < 128) {
            ssim[tid] = sim[e0 + tid];
            slen[tid] = len[e0 + tid];
            sw0[tid] = ew[tid * 2];
            sw1[tid] = ew[tid * 2 + 1];
            sb[tid] = eb[tid];
        }
        __syncthreads();
#pragma unroll
        for (int i = tid; i < 128 * 32; i += 512) {
            int r = i >> 5, c = (i & 31) << 2;
            float s_ = ssim[r], l_ = slen[r];
            float4 v;
            v.x = fmaf(s_, sw0[c + 0], fmaf(l_, sw1[c + 0], sb[c + 0]));
            v.y = fmaf(s_, sw0[c + 1], fmaf(l_, sw1[c + 1], sb[c + 1]));
            v.z = fmaf(s_, sw0[c + 2], fmaf(l_, sw1[c + 2], sb[c + 2]));
            v.w = fmaf(s_, sw0[c + 3], fmaf(l_, sw1[c + 3], sb[c + 3]));
            split_store(ahi, alo, r * SBF + c, v);
        }
    } else {
#pragma unroll
        for (int i = tid; i < 128 * 32; i += 512) {
            int r = i >> 5, c = (i & 31) << 2;
            *(uint2*)(ahi + r * SBF + c) =
                *(const uint2*)(g_e16 + (size_t)(e0 + r) * 128 + c);
        }
    }
    {
        const uint2* wsrc = (const uint2*)(g_Whi + (size_t)(lay * 5 + 4) * 128 * SBF);
        for (int i = tid; i < (128 * SBF) / 4; i += 512) ((uint2*)whi)[i] = wsrc[i];
    }
    __syncthreads();

    float acc[2][4][4];
#pragma unroll
    for (int ms = 0; ms < 2; ms++)
#pragma unroll
        for (int nt = 0; nt < 4; nt++)
#pragma unroll
            for (int j = 0; j < 4; j++) acc[ms][nt][j] = 0.f;

    if (LAY0)
        mma_mainloop<1>(ahi, alo, whi, m0w, n0w, lane, acc);
    else
        mma_mainloop<0>(ahi, alo, whi, m0w, n0w, lane, acc);

    __syncthreads();      // A tiles dead; Csm aliases them
#pragma unroll
    for (int ms = 0; ms < 2; ms++)
#pragma unroll
        for (int nt = 0; nt < 4; nt++) {
            int col = n0w + nt * 8 + (lane & 3) * 2;
            int r0 = m0w + ms * 16 + (lane >> 2);
            *(float2*)(Csm + r0 * SCF + col) = make_float2(acc[ms][nt][0], acc[ms][nt][1]);
            *(float2*)(Csm + (r0 + 8) * SCF + col) = make_float2(acc[ms][nt][2], acc[ms][nt][3]);
        }
    __syncthreads();

    // add Cb + Dh[dst] + Eh[src] in Csm (16 warps x 8 rows), accumulate stats
    int colg = (tid & 31) << 2;
    int r0 = (tid >> 5) << 3;
    float4 cb4 = *(const float4*)(Cb + colg);
    float s0 = 0.f, s1 = 0.f, s2 = 0.f, s3 = 0.f;
    float q0 = 0.f, q1 = 0.f, q2 = 0.f, q3 = 0.f;
#pragma unroll
    for (int j = 0; j < 8; j++) {
        int r = r0 + j;
        float* crow = Csm + r * SCF + colg;
        float4 c = *(const float4*)crow;
        int dd = s_dst[r], sr = s_src[r];
        float4 dh = *(const float4*)(g_Dh + (size_t)dd * 128 + colg);
        float4 eh = *(const float4*)(g_Eh + (size_t)sr * 128 + colg);
        float4 v;
        v.x = c.x + cb4.x + dh.x + eh.x;
        v.y = c.y + cb4.y + dh.y + eh.y;
        v.z = c.z + cb4.z + dh.z + eh.z;
        v.w = c.w + cb4.w + dh.w + eh.w;
        *(float4*)crow = v;
        s0 += v.x; q0 += v.x * v.x;
        s1 += v.y; q1 += v.y * v.y;
        s2 += v.z; q2 += v.z * v.z;
        s3 += v.w; q3 += v.w * v.w;
    }
    atomicAdd(&ssum[colg + 0], s0); atomicAdd(&ssq[colg + 0], q0);
    atomicAdd(&ssum[colg + 1], s1); atomicAdd(&ssq[colg + 1], q1);
    atomicAdd(&ssum[colg + 2], s2); atomicAdd(&ssq[colg + 2], q2);
    atomicAdd(&ssum[colg + 3], s3); atomicAdd(&ssq[colg + 3], q3);
    __syncthreads();

    // coalesced fp16 ehat store
    for (int i = tid; i < 128 * 32; i += 512) {
        int r = i >> 5, c4 = (i & 31) << 2;
        float4 v = *(const float4*)(Csm + r * SCF + c4);
        half2 p0 = __floats2half2_rn(v.x, v.y);
        half2 p1 = __floats2half2_rn(v.z, v.w);
        *(uint2*)(g_ehat + (size_t)(e0 + r) * 128 + c4) =
            make_uint2(*(unsigned*)&p0, *(unsigned*)&p1);
    }
    if (tid < 128) {
        atomicAdd(&g_stats_e[tid], ssum[tid]);
        atomicAdd(&g_stats_e[128 + tid], ssq[tid]);
    }
}

// ---------------- fused agg (1 node/block, smem-staged edges) ----------------
// computes edge-BN locally from g_stats_e; e update + aggregation + t + node stats
__global__ __launch_bounds__(128) void k_agg_fused(const int* __restrict__ src,
                                                   const float* __restrict__ sim,
                                                   const float* __restrict__ len,
                                                   const float* __restrict__ ew,
                                                   const float* __restrict__ eb,
                                                   const float* __restrict__ bng,
                                                   const float* __restrict__ bnb,
                                                   int lay)
{
    __shared__ int s_eid[64];
    __shared__ int s_srcn[64];
    int n = blockIdx.x;
    int d = threadIdx.x;
    int beg = g_off[n], end = g_off[n + 1];

    // local edge-BN finalize
    const float invE = 1.f / (float)N_EDGES;
    float es = g_stats_e[d], eq = g_stats_e[128 + d];
    float mean = es * invE;
    float var = eq * invE - mean * mean;
    float sc = bng[d] * rsqrtf(var + EPS_BN);
    float sh = bnb[d] - mean * sc;

    float w0 = 0.f, w1 = 0.f, b0 = 0.f;
    if (lay == 0) {
        w0 = ew[d * 2];
        w1 = ew[d * 2 + 1];
        b0 = eb[d];
    }
    float num = 0.f, den = 0.f;
    for (int c0 = beg; c0 < end; c0 += 64) {
        int m = end - c0;
        if (m > 64) m = 64;
        __syncthreads();
        if (d < m) {
            int e = g_eids[c0 + d];
            s_eid[d] = e;
            s_srcn[d] = src[e];
        }
        __syncthreads();
#pragma unroll 2
        for (int j = 0; j < m; j++) {
            int eid = s_eid[j];
            float x = __half2float(g_ehat[(size_t)eid * 128 + d]);
            float bh = g_Bh[(size_t)s_srcn[j] * 128 + d];
            float s = 1.f / (1.f + __expf(-x));
            num += s * bh;
            den += s;
            float rel = fmaxf(fmaf(x, sc, sh), 0.f);
            half* ep = g_e16 + (size_t)eid * 128 + d;
            if (lay == 0) {
                float e0v = fmaf(sim[eid], w0, fmaf(len[eid], w1, b0));
                *ep = __float2half_rn(e0v + rel);
            } else {
                *ep = __float2half_rn(__half2float(*ep) + rel);
            }
        }
    }
    float t = g_Ah[n * 128 + d] + num / (den + EPS_AGG);
    g_t[n * 128 + d] = t;
    atomicAdd(&g_stats_n[d], t);
    atomicAdd(&g_stats_n[128 + d], t * t);
}

// ---------------- h += relu(bn(t)); node-BN computed locally; block0 zeroes edge stats --
__global__ __launch_bounds__(256) void k_node_update(const float* __restrict__ bng,
                                                     const float* __restrict__ bnb)
{
    if (blockIdx.x == 0 && threadIdx.x < 256) g_stats_e[threadIdx.x] = 0.f;
    int i = blockIdx.x * 256 + threadIdx.x;
    int d4 = (i & 31) << 2;
    const float invN = 1.f / (float)N_NODES;
    float4 sc, sh;
    {
        float4 s = *(const float4*)(g_stats_n + d4);
        float4 q = *(const float4*)(g_stats_n + 128 + d4);
        float4 g = *(const float4*)(bng + d4);
        float4 b = *(const float4*)(bnb + d4);
        float m0 = s.x * invN, m1 = s.y * invN, m2 = s.z * invN, m3 = s.w * invN;
        sc.x = g.x * rsqrtf(q.x * invN - m0 * m0 + EPS_BN);
        sc.y = g.y * rsqrtf(q.y * invN - m1 * m1 + EPS_BN);
        sc.z = g.z * rsqrtf(q.z * invN - m2 * m2 + EPS_BN);
        sc.w = g.w * rsqrtf(q.w * invN - m3 * m3 + EPS_BN);
        sh.x = b.x - m0 * sc.x;
        sh.y = b.y - m1 * sc.y;
        sh.z = b.z - m2 * sc.z;
        sh.w = b.w - m3 * sc.w;
    }
    float4 x = ((const float4*)g_t)[i];
    float4 hv = ((const float4*)g_h)[i];
    hv.x += fmaxf(fmaf(x.x, sc.x, sh.x), 0.f);
    hv.y += fmaxf(fmaf(x.y, sc.y, sh.y), 0.f);
    hv.z += fmaxf(fmaf(x.z, sc.z, sh.z), 0.f);
    hv.w += fmaxf(fmaf(x.w, sc.w, sh.w), 0.f);
    ((float4*)g_h)[i] = hv;
}

// ---------------- decoder ----------------
__global__ __launch_bounds__(256) void k_dec(const float* __restrict__ dw,
                                             const float* __restrict__ db,
                                             const int* __restrict__ src,
                                             const int* __restrict__ dst,
                                             float* __restrict__ out)
{
    int w = (blockIdx.x * 256 + threadIdx.x) >> 5;
    if (w >= N_EDGES) return;
    int lane = threadIdx.x & 31;
    int s = src[w], d = dst[w];
    float4 w1 = *(const float4*)(dw + lane * 4);
    float4 w2 = *(const float4*)(dw + 128 + lane * 4);
    float4 w3 = *(const float4*)(dw + 256 + lane * 4);
    float4 hs = *(const float4*)(g_h + (size_t)s * 128 + lane * 4);
    float4 hd = *(const float4*)(g_h + (size_t)d * 128 + lane * 4);
    uint2 ep = *(const uint2*)(g_e16 + (size_t)w * 128 + lane * 4);
    half2 e01 = *(half2*)&ep.x, e23 = *(half2*)&ep.y;
    float2 ef0 = __half22float2(e01), ef1 = __half22float2(e23);
    float acc = w1.x * hs.x + w1.y * hs.y + w1.z * hs.z + w1.w * hs.w
              + w2.x * hd.x + w2.y * hd.y + w2.z * hd.z + w2.w * hd.w
              + w3.x * ef0.x + w3.y * ef0.y + w3.z * ef1.x + w3.w * ef1.y;
#pragma unroll
    for (int ofs = 16; ofs > 0; ofs >>= 1) acc += __shfl_down_sync(0xffffffffu, acc, ofs);
    if (lane == 0) out[w] = acc + db[0];
}

// ---------------- launcher ----------------
extern "C" void kernel_launch(void* const* d_in, const int* in_sizes, int n_in,
                              void* d_out, int out_size)
{
    const float* emb    = (const float*)d_in[0];
    const float* conv_w = (const float*)d_in[1];
    const float* conv_b = (const float*)d_in[2];
    const float* ee_w   = (const float*)d_in[3];
    const float* ee_b   = (const float*)d_in[4];
    const float* Aw     = (const float*)d_in[5];
    const float* Ab     = (const float*)d_in[6];
    const float* Bw     = (const float*)d_in[7];
    const float* Bb     = (const float*)d_in[8];
    const float* Cw     = (const float*)d_in[9];
    const float* Cb     = (const float*)d_in[10];
    const float* Dw     = (const float*)d_in[11];
    const float* Db     = (const float*)d_in[12];
    const float* Ew     = (const float*)d_in[13];
    const float* Eb     = (const float*)d_in[14];
    const float* bnh_g  = (const float*)d_in[15];
    const float* bnh_b  = (const float*)d_in[16];
    const float* bne_g  = (const float*)d_in[17];
    const float* bne_b  = (const float*)d_in[18];
    const float* dec_w  = (const float*)d_in[19];
    const float* dec_b  = (const float*)d_in[20];
    const float* sim    = (const float*)d_in[21];
    const float* length = (const float*)d_in[22];
    const int*   reads  = (const int*)d_in[23];
    const int*   src    = (const int*)d_in[24];
    const int*   dst    = (const int*)d_in[25];
    float* out = (float*)d_out;

    const int smemG = 3 * 128 * SBF * 2;                  // 104448 -> 2 blocks/SM
    const int smemE = smemG + 9 * 128 * 4;                 // 109056 -> 2 blocks/SM
    const int smemS = (10 * 16 * DIM) * 4 + 2 * 512 * 4;   // 86016
    cudaFuncSetAttribute(k_node_gemm, cudaFuncAttributeMaxDynamicSharedMemorySize, smemG);
    cudaFuncSetAttribute(k_edge_pass1<true>, cudaFuncAttributeMaxDynamicSharedMemorySize, smemE);
    cudaFuncSetAttribute(k_edge_pass1<false>, cudaFuncAttributeMaxDynamicSharedMemorySize, smemE);
    cudaFuncSetAttribute(k_seq, cudaFuncAttributeMaxDynamicSharedMemorySize, smemS);

    k_wsum<<<40, 256>>>(emb, conv_w);                                   // 0
    k_wsplit<<<20, 256>>>(Aw, Bw, Cw, Dw, Ew);                          // 1
    k_W2<<<(10 * 16 * DIM + 255) / 256, 256>>>();                       // 2
    k_seq<<<N_NODES / 8, 512, smemS>>>(reads, conv_b);                  // 3
    k_node_gemm<<<(N_NODES + 127) / 128, 512, smemG>>>(                 // 4
        0, Ab, Bb, Db, Eb);
    k_edge_pass1<true><<<N_EDGES / 128, 512, smemE>>>(                  // 5
        0, Cb, src, dst, sim, length, ee_w, ee_b);

    k_csr_zero<<<(N_NODES + 255) / 256, 256>>>();
    k_hist<<<N_EDGES / 256, 256>>>(dst);
    k_scan<<<1, 1024>>>();
    k_scatter<<<N_EDGES / 256, 256>>>(dst);

    k_agg_fused<<<N_NODES, 128>>>(src, sim, length, ee_w, ee_b,
                                  bne_g, bne_b, 0);
    k_node_update<<<(N_NODES * 32) / 256, 256>>>(bnh_g, bnh_b);

    for (int i = 1; i < N_LAYERS; i++) {
        const int bo = i * DIM;
        k_node_gemm<<<(N_NODES + 127) / 128, 512, smemG>>>(
            i, Ab + bo, Bb + bo, Db + bo, Eb + bo);
        k_edge_pass1<false><<<N_EDGES / 128, 512, smemE>>>(
            i, Cb + bo, src, dst, sim, length, ee_w, ee_b);
        k_agg_fused<<<N_NODES, 128>>>(src, sim, length, ee_w, ee_b,
                                      bne_g + bo, bne_b + bo, i);
        k_node_update<<<(N_NODES * 32) / 256, 256>>>(bnh_g + bo, bnh_b + bo);
    }
    k_dec<<<(N_EDGES * 32 + 255) / 256, 256>>>(dec_w, dec_b, src, dst, out);
}

// round 17
// speedup vs baseline: 1.2989x; 1.0264x over previous
#include <cuda_runtime.h>
#include <cuda_fp16.h>
#include <cstdint>

#define N_NODES 20000
#define READ_LEN 64
#define N_EDGES 320000
#define DIM 128
#define KSZ 20
#define CONV_T (READ_LEN - KSZ + 1)
#define N_LAYERS 4
#define EPS_BN 1e-5f
#define EPS_AGG 1e-6f

#define SBF 136   // half smem row stride (272B): 16B-aligned rows, ldsm conflict-free
#define SCF 132   // fp32 C smem row stride

// ---------------- device scratch ----------------
__device__ float g_h[N_NODES * DIM];
__device__ half  g_e16[(size_t)N_EDGES * DIM];       // fp16 e
__device__ half  g_ehat[(size_t)N_EDGES * DIM];      // fp16 ehat
__device__ float g_Ah[N_NODES * DIM];
__device__ float g_Bh[N_NODES * DIM];
__device__ float g_Dh[N_NODES * DIM];
__device__ float g_Eh[N_NODES * DIM];
__device__ float g_t[N_NODES * DIM];
__device__ float g_wsum[4 * KSZ * DIM];
__device__ half  g_W2h[10 * 16 * DIM];               // fp16 pair table
__device__ half  g_Whi[20 * 128 * SBF];              // pre-split weights (smem image)
__device__ float g_stats_e[2 * DIM];                 // edge BN stats (zero between uses)
__device__ float g_stats_n[2 * DIM];                 // node BN stats (zero between uses)
__device__ int g_cnt[N_NODES];
__device__ int g_off[N_NODES + 1];
__device__ int g_cur[N_NODES];
__device__ int g_eids[N_EDGES];

// ---------------- mma helpers ----------------
__device__ __forceinline__ unsigned s2u(const void* p)
{
    return (unsigned)__cvta_generic_to_shared(p);
}
__device__ __forceinline__ void ldsm4(unsigned* r, unsigned addr)
{
    asm volatile("ldmatrix.sync.aligned.m8n8.x4.shared.b16 {%0,%1,%2,%3}, [%4];"
                 : "=r"(r[0]), "=r"(r[1]), "=r"(r[2]), "=r"(r[3]) : "r"(addr));
}
__device__ __forceinline__ void mma16816(float* c, const unsigned* a, const unsigned* b)
{
    asm volatile("mma.sync.aligned.m16n8k16.row.col.f32.f16.f16.f32 "
                 "{%0,%1,%2,%3}, {%4,%5,%6,%7}, {%8,%9}, {%0,%1,%2,%3};"
                 : "+f"(c[0]), "+f"(c[1]), "+f"(c[2]), "+f"(c[3])
                 : "r"(a[0]), "r"(a[1]), "r"(a[2]), "r"(a[3]), "r"(b[0]), "r"(b[1]));
}

// pack 4 fp32 into hi/lo fp16 pairs and store to smem tile offset
__device__ __forceinline__ void split_store(half* hi, half* lo, int off4, float4 v)
{
    half hx = __float2half_rn(v.x), hy = __float2half_rn(v.y);
    half hz = __float2half_rn(v.z), hw = __float2half_rn(v.w);
    half2 hp0 = __halves2half2(hx, hy), hp1 = __halves2half2(hz, hw);
    half2 lp0 = __floats2half2_rn(v.x - __half2float(hx), v.y - __half2float(hy));
    half2 lp1 = __floats2half2_rn(v.z - __half2float(hz), v.w - __half2float(hw));
    *(uint2*)(hi + off4) = make_uint2(*(unsigned*)&hp0, *(unsigned*)&hp1);
    *(uint2*)(lo + off4) = make_uint2(*(unsigned*)&lp0, *(unsigned*)&lp1);
}

// split fp32 tile [rows<=128][128] into hi/lo fp16 smem tiles (512 threads)
__device__ __forceinline__ void split_tileA(const float* __restrict__ g, int rows,
                                            half* hi, half* lo, int tid)
{
#pragma unroll
    for (int i = tid; i < 128 * 32; i += 512) {
        int r = i >> 5, c = (i & 31) << 2;
        float4 v = make_float4(0.f, 0.f, 0.f, 0.f);
        if (r < rows) v = *(const float4*)(g + r * 128 + c);
        split_store(hi, lo, r * SBF + c, v);
    }
}

// mainloop (per warp, 32x32 tile): TWO=1: acc += Ahi*W + Alo*W; TWO=0: acc += Ahi*W
template <int TWO>
__device__ __forceinline__ void mma_mainloop(const half* ahi, const half* alo,
                                             const half* whi,
                                             int m0w, int n0w, int lane,
                                             float acc[2][4][4])
{
    int aoff = (lane & 15) * SBF + (lane >> 4) * 8;
    int boff = ((lane & 7) + ((lane >> 4) << 3)) * SBF + ((lane >> 3) & 1) * 8;
#pragma unroll
    for (int kt = 0; kt < 8; kt++) {
        unsigned bf[2][4];
#pragma unroll
        for (int np = 0; np < 2; np++) {
            int o = (n0w + np * 16) * SBF + boff + kt * 16;
            ldsm4(bf[np], s2u(whi + o));
        }
        unsigned af[2][4];
#pragma unroll
        for (int ms = 0; ms < 2; ms++) {
            int o = (m0w + ms * 16) * SBF + aoff + kt * 16;
            ldsm4(af[ms], s2u(ahi + o));
        }
#pragma unroll
        for (int ms = 0; ms < 2; ms++)
#pragma unroll
            for (int nt = 0; nt < 4; nt++)
                mma16816(acc[ms][nt], af[ms], &bf[nt >> 1][(nt & 1) * 2]);
        if (TWO) {
#pragma unroll
            for (int ms = 0; ms < 2; ms++) {
                int o = (m0w + ms * 16) * SBF + aoff + kt * 16;
                ldsm4(af[ms], s2u(alo + o));      // overwrite hi frags
            }
#pragma unroll
            for (int ms = 0; ms < 2; ms++)
#pragma unroll
                for (int nt = 0; nt < 4; nt++)
                    mma16816(acc[ms][nt], af[ms], &bf[nt >> 1][(nt & 1) * 2]);
        }
    }
}

// ---------------- prep ----------------
__global__ void k_wsum(const float* __restrict__ emb, const float* __restrict__ cw)
{
    int idx = blockIdx.x * 256 + threadIdx.x;
    if (idx >= 4 * KSZ * DIM) return;
    int d = idx & 127;
    int bk = idx >> 7;
    int k = bk % KSZ, b = bk / KSZ;
    float s = 0.f;
#pragma unroll
    for (int c = 0; c < 3; c++) s += emb[b * 3 + c] * cw[d * 3 * KSZ + c * KSZ + k];
    g_wsum[idx] = s;
}

__global__ void k_wsplit(const float* __restrict__ Aw, const float* __restrict__ Bw,
                         const float* __restrict__ Cw, const float* __restrict__ Dw,
                         const float* __restrict__ Ew)
{
    int m = blockIdx.x, tid = threadIdx.x;   // 20 blocks
    int lay = m / 5, which = m % 5;
    const float* srcs[5] = {Aw, Bw, Dw, Ew, Cw};
    const float* src = srcs[which] + lay * DIM * DIM;
    half* dst = g_Whi + (size_t)m * 128 * SBF;
    for (int i = tid; i < 128 * 128; i += 256) {
        int r = i >> 7, c = i & 127;
        dst[r * SBF + c] = __float2half_rn(src[i]);
    }
}

__global__ void k_W2()
{
    int idx = blockIdx.x * 256 + threadIdx.x;
    if (idx >= 10 * 16 * DIM) return;
    int d = idx & 127;
    int r = idx >> 7;
    int c2 = r & 15, k2 = r >> 4;
    int a = c2 >> 2, b = c2 & 3;
    g_W2h[idx] = __float2half_rn(
        g_wsum[(a * KSZ + 2 * k2) * DIM + d] + g_wsum[(b * KSZ + 2 * k2 + 1) * DIM + d]);
}

__global__ __launch_bounds__(512) void k_seq(const int* __restrict__ reads,
                                             const float* __restrict__ conv_b)
{
    extern __shared__ char smsc[];
    half* sW2 = (half*)smsc;                       // 10*16*128 halves = 40960 B
    int* scode = (int*)(smsc + 10 * 16 * DIM * 2);
    int* spc = scode + 512;
    int tid = threadIdx.x;

    for (int i = tid; i < (10 * 16 * DIM * 2) / 16; i += 512)
        ((uint4*)sW2)[i] = ((const uint4*)g_W2h)[i];

    int nl = tid >> 6, l = tid & 63;
    int n = blockIdx.x * 8 + nl;
    scode[tid] = reads[n * READ_LEN + l];
    __syncthreads();
    if (l < 63) spc[tid] = (scode[tid] * 4 + scode[tid + 1]) << 7;
    __syncthreads();

    int dp = tid & 63;
    const half* wd = sW2 + dp * 2;
    const int* pc = spc + nl * 64;
    float m0 = -3.4e38f, m1 = -3.4e38f;
#pragma unroll
    for (int t = 0; t < CONV_T; t++) {
        float s0 = 0.f, s1 = 0.f;
#pragma unroll
        for (int k2 = 0; k2 < 10; k2++) {
            float2 v = __half22float2(*(const half2*)(wd + pc[t + 2 * k2] + k2 * 2048));
            s0 += v.x; s1 += v.y;
        }
        m0 = fmaxf(m0, s0);
        m1 = fmaxf(m1, s1);
    }
    float2 bv = *(const float2*)(conv_b + dp * 2);
    float2 hv;
    hv.x = fmaxf(m0 + bv.x, 0.f);
    hv.y = fmaxf(m1 + bv.y, 0.f);
    *(float2*)(g_h + n * DIM + dp * 2) = hv;
}

// ---------------- CSR build by dst ----------------
__global__ void k_csr_zero()
{
    int i = blockIdx.x * 256 + threadIdx.x;
    if (i < N_NODES) g_cnt[i] = 0;
}
__global__ void k_hist(const int* __restrict__ dst)
{
    int i = blockIdx.x * 256 + threadIdx.x;
    if (i < N_EDGES) atomicAdd(&g_cnt[dst[i]], 1);
}
__global__ __launch_bounds__(1024) void k_scan()
{
    __shared__ int sd[1024];
    int tid = threadIdx.x;
    int carry = 0;
    for (int base = 0; base < N_NODES; base += 1024) {
        int i = base + tid;
        int v = (i < N_NODES) ? g_cnt[i] : 0;
        __syncthreads();
        sd[tid] = v;
        __syncthreads();
        for (int ofs = 1; ofs < 1024; ofs <<= 1) {
            int t = (tid >= ofs) ? sd[tid - ofs] : 0;
            __syncthreads();
            sd[tid] += t;
            __syncthreads();
        }
        if (i < N_NODES) {
            int ex = carry + sd[tid] - v;
            g_off[i] = ex;
            g_cur[i] = ex;
        }
        carry += sd[1023];
    }
    if (tid == 0) g_off[N_NODES] = carry;
}
__global__ void k_scatter(const int* __restrict__ dst)
{
    int i = blockIdx.x * 256 + threadIdx.x;
    if (i < N_EDGES) {
        int p = atomicAdd(&g_cur[dst[i]], 1);
        g_eids[p] = i;
    }
}

// ---------------- node GEMM: (optional fused h-update) then Ah,Bh,Dh,Eh = h @ W.T + b ----
// ubng != nullptr: h += relu(bn(t)) fused into the A-load (node BN from g_stats_n);
// block 0 also zeroes g_stats_e for the upcoming pass1.
__global__ __launch_bounds__(512, 2) void k_node_gemm(
    int lay,
    const float* __restrict__ Ba, const float* __restrict__ Bb_,
    const float* __restrict__ Bd, const float* __restrict__ Be,
    const float* __restrict__ ubng, const float* __restrict__ ubnb)
{
    const float* Bp[4] = {Ba, Bb_, Bd, Be};
    float* Op[4] = {g_Ah, g_Bh, g_Dh, g_Eh};
    extern __shared__ char smc[];
    half* ahi = (half*)smc;
    half* alo = ahi + 128 * SBF;
    half* whi = alo + 128 * SBF;
    float* sscale = (float*)(smc + 3 * 128 * SBF * 2);
    float* sshift = sscale + 128;

    int tid = threadIdx.x;
    int lane = tid & 31, w = tid >> 5;
    int m0w = (w & 3) * 32, n0w = (w >> 2) * 32;
    int n0 = blockIdx.x * 128;
    int mlim = N_NODES - n0;
    if (mlim > 128) mlim = 128;

    if (ubng) {
        if (tid < 128) {
            const float invN = 1.f / (float)N_NODES;
            float s = g_stats_n[tid], q = g_stats_n[128 + tid];
            float m = s * invN;
            float v = q * invN - m * m;
            float sc = ubng[tid] * rsqrtf(v + EPS_BN);
            sscale[tid] = sc;
            sshift[tid] = ubnb[tid] - m * sc;
        }
        if (blockIdx.x == 0 && tid >= 128 && tid < 384) g_stats_e[tid - 128] = 0.f;
        __syncthreads();
#pragma unroll
        for (int i = tid; i < 128 * 32; i += 512) {
            int r = i >> 5, c = (i & 31) << 2;
            float4 v = make_float4(0.f, 0.f, 0.f, 0.f);
            if (r < mlim) {
                float4 t4 = *(const float4*)(g_t + (size_t)(n0 + r) * 128 + c);
                float4 h4 = *(const float4*)(g_h + (size_t)(n0 + r) * 128 + c);
                float4 sc4 = *(const float4*)(sscale + c);
                float4 sh4 = *(const float4*)(sshift + c);
                v.x = h4.x + fmaxf(fmaf(t4.x, sc4.x, sh4.x), 0.f);
                v.y = h4.y + fmaxf(fmaf(t4.y, sc4.y, sh4.y), 0.f);
                v.z = h4.z + fmaxf(fmaf(t4.z, sc4.z, sh4.z), 0.f);
                v.w = h4.w + fmaxf(fmaf(t4.w, sc4.w, sh4.w), 0.f);
                *(float4*)(g_h + (size_t)(n0 + r) * 128 + c) = v;
            }
            split_store(ahi, alo, r * SBF + c, v);
        }
    } else {
        split_tileA(g_h + (size_t)n0 * 128, mlim, ahi, alo, tid);
    }

    for (int mat = 0; mat < 4; mat++) {
        __syncthreads();
        const uint2* wsrc = (const uint2*)(g_Whi + (size_t)(lay * 5 + mat) * 128 * SBF);
        for (int i = tid; i < (128 * SBF) / 4; i += 512) ((uint2*)whi)[i] = wsrc[i];
        __syncthreads();
        float acc[2][4][4];
#pragma unroll
        for (int ms = 0; ms < 2; ms++)
#pragma unroll
            for (int nt = 0; nt < 4; nt++)
#pragma unroll
                for (int j = 0; j < 4; j++) acc[ms][nt][j] = 0.f;

        mma_mainloop<1>(ahi, alo, whi, m0w, n0w, lane, acc);

        float* Out = Op[mat];
        const float* Bias = Bp[mat];
#pragma unroll
        for (int ms = 0; ms < 2; ms++)
#pragma unroll
            for (int nt = 0; nt < 4; nt++) {
                int col = n0w + nt * 8 + (lane & 3) * 2;
                float2 bv = *(const float2*)(Bias + col);
                int r0 = m0w + ms * 16 + (lane >> 2);
                if (r0 < mlim) {
                    float2 v = {acc[ms][nt][0] + bv.x, acc[ms][nt][1] + bv.y};
                    *(float2*)(Out + (size_t)(n0 + r0) * 128 + col) = v;
                }
                if (r0 + 8 < mlim) {
                    float2 v = {acc[ms][nt][2] + bv.x, acc[ms][nt][3] + bv.y};
                    *(float2*)(Out + (size_t)(n0 + r0 + 8) * 128 + col) = v;
                }
            }
    }
}

// ---------------- edge pass1: ehat = e@Cw.T + Cb + Dh[dst] + Eh[src]; edge BN stats ----
// LAY0: e tile computed from sim/len/ee_w/ee_b (two-term split)
// else: e tile copied from fp16 g_e16 (single-term). Block 0 zeroes g_stats_n.
template <bool LAY0>
__global__ __launch_bounds__(512, 2) void k_edge_pass1(int lay,
                                                       const float* __restrict__ Cb,
                                                       const int* __restrict__ src,
                                                       const int* __restrict__ dst,
                                                       const float* __restrict__ sim,
                                                       const float* __restrict__ len,
                                                       const float* __restrict__ ew,
                                                       const float* __restrict__ eb)
{
    extern __shared__ char smc[];
    half* ahi = (half*)smc;
    half* alo = ahi + 128 * SBF;
    half* whi = alo + 128 * SBF;
    float* Csm = (float*)smc;                     // aliases ahi/alo after mma
    char* tail = smc + 3 * 128 * SBF * 2;
    int* s_src = (int*)tail;
    int* s_dst = s_src + 128;
    float* ssum = (float*)(s_dst + 128);
    float* ssq = ssum + 128;
    float* ssim = ssq + 128;
    float* slen = ssim + 128;
    float* sw0 = slen + 128;
    float* sw1 = sw0 + 128;
    float* sb = sw1 + 128;

    int tid = threadIdx.x;
    int lane = tid & 31, w = tid >> 5;
    int m0w = (w & 3) * 32, n0w = (w >> 2) * 32;
    int e0 = blockIdx.x * 128;

    if (blockIdx.x == 0 && tid < 256) g_stats_n[tid] = 0.f;

    if (tid < 128) {
        s_src[tid] = src[e0 + tid];
        s_dst[tid] = dst[e0 + tid];
        ssum[tid] = 0.f;
        ssq[tid] = 0.f;
    }
    if (LAY0) {
        if (tid < 128) {
            ssim[tid] = sim[e0 + tid];
            slen[tid] = len[e0 + tid];
            sw0[tid] = ew[tid * 2];
            sw1[tid] = ew[tid * 2 + 1];
            sb[tid] = eb[tid];
        }
        __syncthreads();
#pragma unroll
        for (int i = tid; i < 128 * 32; i += 512) {
            int r = i >> 5, c = (i & 31) << 2;
            float s_ = ssim[r], l_ = slen[r];
            float4 v;
            v.x = fmaf(s_, sw0[c + 0], fmaf(l_, sw1[c + 0], sb[c + 0]));
            v.y = fmaf(s_, sw0[c + 1], fmaf(l_, sw1[c + 1], sb[c + 1]));
            v.z = fmaf(s_, sw0[c + 2], fmaf(l_, sw1[c + 2], sb[c + 2]));
            v.w = fmaf(s_, sw0[c + 3], fmaf(l_, sw1[c + 3], sb[c + 3]));
            split_store(ahi, alo, r * SBF + c, v);
        }
    } else {
#pragma unroll
        for (int i = tid; i < 128 * 32; i += 512) {
            int r = i >> 5, c = (i & 31) << 2;
            *(uint2*)(ahi + r * SBF + c) =
                *(const uint2*)(g_e16 + (size_t)(e0 + r) * 128 + c);
        }
    }
    {
        const uint2* wsrc = (const uint2*)(g_Whi + (size_t)(lay * 5 + 4) * 128 * SBF);
        for (int i = tid; i < (128 * SBF) / 4; i += 512) ((uint2*)whi)[i] = wsrc[i];
    }
    __syncthreads();

    float acc[2][4][4];
#pragma unroll
    for (int ms = 0; ms < 2; ms++)
#pragma unroll
        for (int nt = 0; nt < 4; nt++)
#pragma unroll
            for (int j = 0; j < 4; j++) acc[ms][nt][j] = 0.f;

    if (LAY0)
        mma_mainloop<1>(ahi, alo, whi, m0w, n0w, lane, acc);
    else
        mma_mainloop<0>(ahi, alo, whi, m0w, n0w, lane, acc);

    __syncthreads();      // A tiles dead; Csm aliases them
#pragma unroll
    for (int ms = 0; ms < 2; ms++)
#pragma unroll
        for (int nt = 0; nt < 4; nt++) {
            int col = n0w + nt * 8 + (lane & 3) * 2;
            int r0 = m0w + ms * 16 + (lane >> 2);
            *(float2*)(Csm + r0 * SCF + col) = make_float2(acc[ms][nt][0], acc[ms][nt][1]);
            *(float2*)(Csm + (r0 + 8) * SCF + col) = make_float2(acc[ms][nt][2], acc[ms][nt][3]);
        }
    __syncthreads();

    int colg = (tid & 31) << 2;
    int r0 = (tid >> 5) << 3;
    float4 cb4 = *(const float4*)(Cb + colg);
    float s0 = 0.f, s1 = 0.f, s2 = 0.f, s3 = 0.f;
    float q0 = 0.f, q1 = 0.f, q2 = 0.f, q3 = 0.f;
#pragma unroll
    for (int j = 0; j < 8; j++) {
        int r = r0 + j;
        float* crow = Csm + r * SCF + colg;
        float4 c = *(const float4*)crow;
        int dd = s_dst[r], sr = s_src[r];
        float4 dh = *(const float4*)(g_Dh + (size_t)dd * 128 + colg);
        float4 eh = *(const float4*)(g_Eh + (size_t)sr * 128 + colg);
        float4 v;
        v.x = c.x + cb4.x + dh.x + eh.x;
        v.y = c.y + cb4.y + dh.y + eh.y;
        v.z = c.z + cb4.z + dh.z + eh.z;
        v.w = c.w + cb4.w + dh.w + eh.w;
        *(float4*)crow = v;
        s0 += v.x; q0 += v.x * v.x;
        s1 += v.y; q1 += v.y * v.y;
        s2 += v.z; q2 += v.z * v.z;
        s3 += v.w; q3 += v.w * v.w;
    }
    atomicAdd(&ssum[colg + 0], s0); atomicAdd(&ssq[colg + 0], q0);
    atomicAdd(&ssum[colg + 1], s1); atomicAdd(&ssq[colg + 1], q1);
    atomicAdd(&ssum[colg + 2], s2); atomicAdd(&ssq[colg + 2], q2);
    atomicAdd(&ssum[colg + 3], s3); atomicAdd(&ssq[colg + 3], q3);
    __syncthreads();

    for (int i = tid; i < 128 * 32; i += 512) {
        int r = i >> 5, c4 = (i & 31) << 2;
        float4 v = *(const float4*)(Csm + r * SCF + c4);
        half2 p0 = __floats2half2_rn(v.x, v.y);
        half2 p1 = __floats2half2_rn(v.z, v.w);
        *(uint2*)(g_ehat + (size_t)(e0 + r) * 128 + c4) =
            make_uint2(*(unsigned*)&p0, *(unsigned*)&p1);
    }
    if (tid < 128) {
        atomicAdd(&g_stats_e[tid], ssum[tid]);
        atomicAdd(&g_stats_e[128 + tid], ssq[tid]);
    }
}

// ---------------- fused agg (1 node/block, smem-staged edges) ----------------
__global__ __launch_bounds__(128) void k_agg_fused(const int* __restrict__ src,
                                                   const float* __restrict__ sim,
                                                   const float* __restrict__ len,
                                                   const float* __restrict__ ew,
                                                   const float* __restrict__ eb,
                                                   const float* __restrict__ bng,
                                                   const float* __restrict__ bnb,
                                                   int lay)
{
    __shared__ int s_eid[64];
    __shared__ int s_srcn[64];
    int n = blockIdx.x;
    int d = threadIdx.x;
    int beg = g_off[n], end = g_off[n + 1];

    const float invE = 1.f / (float)N_EDGES;
    float es = g_stats_e[d], eq = g_stats_e[128 + d];
    float mean = es * invE;
    float var = eq * invE - mean * mean;
    float sc = bng[d] * rsqrtf(var + EPS_BN);
    float sh = bnb[d] - mean * sc;

    float w0 = 0.f, w1 = 0.f, b0 = 0.f;
    if (lay == 0) {
        w0 = ew[d * 2];
        w1 = ew[d * 2 + 1];
        b0 = eb[d];
    }
    float num = 0.f, den = 0.f;
    for (int c0 = beg; c0 < end; c0 += 64) {
        int m = end - c0;
        if (m > 64) m = 64;
        __syncthreads();
        if (d < m) {
            int e = g_eids[c0 + d];
            s_eid[d] = e;
            s_srcn[d] = src[e];
        }
        __syncthreads();
#pragma unroll 2
        for (int j = 0; j < m; j++) {
            int eid = s_eid[j];
            float x = __half2float(g_ehat[(size_t)eid * 128 + d]);
            float bh = g_Bh[(size_t)s_srcn[j] * 128 + d];
            float s = 1.f / (1.f + __expf(-x));
            num += s * bh;
            den += s;
            float rel = fmaxf(fmaf(x, sc, sh), 0.f);
            half* ep = g_e16 + (size_t)eid * 128 + d;
            if (lay == 0) {
                float e0v = fmaf(sim[eid], w0, fmaf(len[eid], w1, b0));
                *ep = __float2half_rn(e0v + rel);
            } else {
                *ep = __float2half_rn(__half2float(*ep) + rel);
            }
        }
    }
    float t = g_Ah[n * 128 + d] + num / (den + EPS_AGG);
    g_t[n * 128 + d] = t;
    atomicAdd(&g_stats_n[d], t);
    atomicAdd(&g_stats_n[128 + d], t * t);
}

// ---------------- standalone h += relu(bn(t)) (last layer); block0 zeroes edge stats ----
__global__ __launch_bounds__(256) void k_node_update(const float* __restrict__ bng,
                                                     const float* __restrict__ bnb)
{
    if (blockIdx.x == 0 && threadIdx.x < 256) g_stats_e[threadIdx.x] = 0.f;
    int i = blockIdx.x * 256 + threadIdx.x;
    int d4 = (i & 31) << 2;
    const float invN = 1.f / (float)N_NODES;
    float4 sc, sh;
    {
        float4 s = *(const float4*)(g_stats_n + d4);
        float4 q = *(const float4*)(g_stats_n + 128 + d4);
        float4 g = *(const float4*)(bng + d4);
        float4 b = *(const float4*)(bnb + d4);
        float m0 = s.x * invN, m1 = s.y * invN, m2 = s.z * invN, m3 = s.w * invN;
        sc.x = g.x * rsqrtf(q.x * invN - m0 * m0 + EPS_BN);
        sc.y = g.y * rsqrtf(q.y * invN - m1 * m1 + EPS_BN);
        sc.z = g.z * rsqrtf(q.z * invN - m2 * m2 + EPS_BN);
        sc.w = g.w * rsqrtf(q.w * invN - m3 * m3 + EPS_BN);
        sh.x = b.x - m0 * sc.x;
        sh.y = b.y - m1 * sc.y;
        sh.z = b.z - m2 * sc.z;
        sh.w = b.w - m3 * sc.w;
    }
    float4 x = ((const float4*)g_t)[i];
    float4 hv = ((const float4*)g_h)[i];
    hv.x += fmaxf(fmaf(x.x, sc.x, sh.x), 0.f);
    hv.y += fmaxf(fmaf(x.y, sc.y, sh.y), 0.f);
    hv.z += fmaxf(fmaf(x.z, sc.z, sh.z), 0.f);
    hv.w += fmaxf(fmaf(x.w, sc.w, sh.w), 0.f);
    ((float4*)g_h)[i] = hv;
}

// ---------------- decoder ----------------
__global__ __launch_bounds__(256) void k_dec(const float* __restrict__ dw,
                                             const float* __restrict__ db,
                                             const int* __restrict__ src,
                                             const int* __restrict__ dst,
                                             float* __restrict__ out)
{
    int w = (blockIdx.x * 256 + threadIdx.x) >> 5;
    if (w >= N_EDGES) return;
    int lane = threadIdx.x & 31;
    int s = src[w], d = dst[w];
    float4 w1 = *(const float4*)(dw + lane * 4);
    float4 w2 = *(const float4*)(dw + 128 + lane * 4);
    float4 w3 = *(const float4*)(dw + 256 + lane * 4);
    float4 hs = *(const float4*)(g_h + (size_t)s * 128 + lane * 4);
    float4 hd = *(const float4*)(g_h + (size_t)d * 128 + lane * 4);
    uint2 ep = *(const uint2*)(g_e16 + (size_t)w * 128 + lane * 4);
    half2 e01 = *(half2*)&ep.x, e23 = *(half2*)&ep.y;
    float2 ef0 = __half22float2(e01), ef1 = __half22float2(e23);
    float acc = w1.x * hs.x + w1.y * hs.y + w1.z * hs.z + w1.w * hs.w
              + w2.x * hd.x + w2.y * hd.y + w2.z * hd.z + w2.w * hd.w
              + w3.x * ef0.x + w3.y * ef0.y + w3.z * ef1.x + w3.w * ef1.y;
#pragma unroll
    for (int ofs = 16; ofs > 0; ofs >>= 1) acc += __shfl_down_sync(0xffffffffu, acc, ofs);
    if (lane == 0) out[w] = acc + db[0];
}

// ---------------- launcher ----------------
extern "C" void kernel_launch(void* const* d_in, const int* in_sizes, int n_in,
                              void* d_out, int out_size)
{
    const float* emb    = (const float*)d_in[0];
    const float* conv_w = (const float*)d_in[1];
    const float* conv_b = (const float*)d_in[2];
    const float* ee_w   = (const float*)d_in[3];
    const float* ee_b   = (const float*)d_in[4];
    const float* Aw     = (const float*)d_in[5];
    const float* Ab     = (const float*)d_in[6];
    const float* Bw     = (const float*)d_in[7];
    const float* Bb     = (const float*)d_in[8];
    const float* Cw     = (const float*)d_in[9];
    const float* Cb     = (const float*)d_in[10];
    const float* Dw     = (const float*)d_in[11];
    const float* Db     = (const float*)d_in[12];
    const float* Ew     = (const float*)d_in[13];
    const float* Eb     = (const float*)d_in[14];
    const float* bnh_g  = (const float*)d_in[15];
    const float* bnh_b  = (const float*)d_in[16];
    const float* bne_g  = (const float*)d_in[17];
    const float* bne_b  = (const float*)d_in[18];
    const float* dec_w  = (const float*)d_in[19];
    const float* dec_b  = (const float*)d_in[20];
    const float* sim    = (const float*)d_in[21];
    const float* length = (const float*)d_in[22];
    const int*   reads  = (const int*)d_in[23];
    const int*   src    = (const int*)d_in[24];
    const int*   dst    = (const int*)d_in[25];
    float* out = (float*)d_out;

    const int smemG = 3 * 128 * SBF * 2 + 1024;            // 105472 -> 2 blocks/SM
    const int smemE = 3 * 128 * SBF * 2 + 9 * 128 * 4;     // 109056 -> 2 blocks/SM
    const int smemS = 10 * 16 * DIM * 2 + 2 * 512 * 4;     // 45056
    cudaFuncSetAttribute(k_node_gemm, cudaFuncAttributeMaxDynamicSharedMemorySize, smemG);
    cudaFuncSetAttribute(k_edge_pass1<true>, cudaFuncAttributeMaxDynamicSharedMemorySize, smemE);
    cudaFuncSetAttribute(k_edge_pass1<false>, cudaFuncAttributeMaxDynamicSharedMemorySize, smemE);
    cudaFuncSetAttribute(k_seq, cudaFuncAttributeMaxDynamicSharedMemorySize, smemS);

    k_wsum<<<40, 256>>>(emb, conv_w);                                   // 0
    k_wsplit<<<20, 256>>>(Aw, Bw, Cw, Dw, Ew);                          // 1
    k_W2<<<(10 * 16 * DIM + 255) / 256, 256>>>();                       // 2
    k_seq<<<N_NODES / 8, 512, smemS>>>(reads, conv_b);                  // 3
    k_node_gemm<<<(N_NODES + 127) / 128, 512, smemG>>>(                 // 4
        0, Ab, Bb, Db, Eb, nullptr, nullptr);
    k_edge_pass1<true><<<N_EDGES / 128, 512, smemE>>>(                  // 5
        0, Cb, src, dst, sim, length, ee_w, ee_b);

    k_csr_zero<<<(N_NODES + 255) / 256, 256>>>();
    k_hist<<<N_EDGES / 256, 256>>>(dst);
    k_scan<<<1, 1024>>>();
    k_scatter<<<N_EDGES / 256, 256>>>(dst);

    k_agg_fused<<<N_NODES, 128>>>(src, sim, length, ee_w, ee_b,
                                  bne_g, bne_b, 0);

    for (int i = 1; i < N_LAYERS; i++) {
        const int bo = i * DIM;
        k_node_gemm<<<(N_NODES + 127) / 128, 512, smemG>>>(
            i, Ab + bo, Bb + bo, Db + bo, Eb + bo,
            bnh_g + (i - 1) * DIM, bnh_b + (i - 1) * DIM);
        k_edge_pass1<false><<<N_EDGES / 128, 512, smemE>>>(
            i, Cb + bo, src, dst, sim, length, ee_w, ee_b);
        k_agg_fused<<<N_NODES, 128>>>(src, sim, length, ee_w, ee_b,
                                      bne_g + bo, bne_b + bo, i);
    }
    k_node_update<<<(N_NODES * 32) / 256, 256>>>(bnh_g + 3 * DIM, bnh_b + 3 * DIM);
    k_dec<<<(N_EDGES * 32 + 255) / 256, 256>>>(dec_w, dec_b, src, dst, out);
}